// round 11
// baseline (speedup 1.0000x reference)
#include <cuda_runtime.h>
#include <cstdint>

#define Bq 256
#define Sq 512
#define Eq 256
#define Hq 256
#define G4 1024
#define NB_ENC 128
#define NW 128
#define NB_DEC 256
#define MASKVAL -100000.0f
#define TINYF 1.17549435e-38f
#define CLV 7.90531110763549805f

typedef unsigned long long ull;

// ---------------- device globals (static scratch) ----------------
__device__ float d_emb[(size_t)Sq * Bq * Eq];        // [s][b][e]
__device__ float d_XgEnc[(size_t)Sq * Bq * G4];      // [s][b][j]
__device__ float d_Dg[(size_t)Sq * Bq * G4];         // [s][b][j]
__device__ float d_encout[(size_t)Sq * Bq * Hq];     // [s][b][h]
__device__ float d_refproj[(size_t)Bq * Sq * Hq];    // [b][s][h]
__device__ float d_gum[(size_t)(Sq - 1) * Bq * Sq];  // [t][b][s]
__device__ float d_qpart[(size_t)Bq * 16 * Hq];      // [b][th][j]
__device__ float d_hbuf[2 * Bq * Hq];
__device__ float d_c[Bq * Hq];
__device__ int d_plist[Bq * Sq];
__device__ int d_ppos[Bq * Sq];
__device__ int d_chosen[Bq];
__device__ unsigned int d_keys[(Sq - 1) * 2];
__device__ float d_lp[(Sq - 1) * Bq];
__device__ int d_idx[(Sq - 1) * Bq];
__device__ int d_xgcnt[Sq];
__device__ unsigned int g_enc_done = 0;
__device__ unsigned int g_cnt1[8 * 32];              // padded sub-counters (128B apart)
__device__ unsigned int g_cntr = 0;
__device__ unsigned int g_gen = 0;

// ---------------- f32x2 packed helpers ----------------
__device__ __forceinline__ ull pk2(float lo, float hi) {
    ull r;
    asm("mov.b64 %0, {%1, %2};" : "=l"(r) : "f"(lo), "f"(hi));
    return r;
}
__device__ __forceinline__ void upk2(ull v, float& lo, float& hi) {
    asm("mov.b64 {%0, %1}, %2;" : "=f"(lo), "=f"(hi) : "l"(v));
}
__device__ __forceinline__ ull fma2(ull a, ull b, ull c) {
    ull d;
    asm("fma.rn.f32x2 %0, %1, %2, %3;" : "=l"(d) : "l"(a), "l"(b), "l"(c));
    return d;
}
__device__ __forceinline__ ull mul2(ull a, ull b) {
    ull d;
    asm("mul.rn.f32x2 %0, %1, %2;" : "=l"(d) : "l"(a), "l"(b));
    return d;
}
__device__ __forceinline__ ull pk1(float c) { return pk2(c, c); }

// ---------------- math helpers ----------------
__device__ __forceinline__ float xtanh(float x) {
    float ax = fabsf(x);
    float xc = fminf(fmaxf(x, -CLV), CLV);
    float x2 = xc * xc;
    float p = -2.76076847742355e-16f;
    p = fmaf(p, x2, 2.00018790482477e-13f);
    p = fmaf(p, x2, -8.60467152213735e-11f);
    p = fmaf(p, x2, 5.12229709037114e-08f);
    p = fmaf(p, x2, 1.48572235717979e-05f);
    p = fmaf(p, x2, 6.37261928875436e-04f);
    p = fmaf(p, x2, 4.89352455891786e-03f);
    float q = 1.19825839466702e-06f;
    q = fmaf(q, x2, 1.18534705686654e-04f);
    q = fmaf(q, x2, 2.26843463243900e-03f);
    q = fmaf(q, x2, 4.89352518554385e-03f);
    float t = (xc * p) / q;
    return (ax < 0.0004f) ? x : t;
}

__device__ __forceinline__ ull xtanh2pk(ull X) {
    ull x2 = mul2(X, X);
    ull p = pk1(-2.76076847742355e-16f);
    p = fma2(p, x2, pk1(2.00018790482477e-13f));
    p = fma2(p, x2, pk1(-8.60467152213735e-11f));
    p = fma2(p, x2, pk1(5.12229709037114e-08f));
    p = fma2(p, x2, pk1(1.48572235717979e-05f));
    p = fma2(p, x2, pk1(6.37261928875436e-04f));
    p = fma2(p, x2, pk1(4.89352455891786e-03f));
    ull q = pk1(1.19825839466702e-06f);
    q = fma2(q, x2, pk1(1.18534705686654e-04f));
    q = fma2(q, x2, pk1(2.26843463243900e-03f));
    q = fma2(q, x2, pk1(4.89352518554385e-03f));
    ull num = mul2(X, p);
    float qa, qb;
    upk2(q, qa, qb);
    float ra, rb;
    asm("rcp.approx.f32 %0, %1;" : "=f"(ra) : "f"(qa));
    asm("rcp.approx.f32 %0, %1;" : "=f"(rb) : "f"(qb));
    ull rr = pk2(ra, rb);
    ull nq = q ^ 0x8000000080000000ULL;
    ull e = fma2(nq, rr, pk1(1.0f));
    rr = fma2(e, rr, rr);
    return mul2(num, rr);
}

__device__ __forceinline__ ull clamp_pack(float a, float b) {
    float ca = fminf(fmaxf(a, -CLV), CLV);
    float cb = fminf(fmaxf(b, -CLV), CLV);
    return pk2(ca, cb);
}

__device__ __forceinline__ float xsigmoid(float x) {
    return 1.0f / (1.0f + expf(-x));
}

__device__ __forceinline__ unsigned int rotl32(unsigned int v, int r) {
    return (v << r) | (v >> (32 - r));
}

__device__ __forceinline__ void threefry2x32(unsigned int k0, unsigned int k1,
                                             unsigned int x0, unsigned int x1,
                                             unsigned int& o0, unsigned int& o1) {
    unsigned int ks2 = k0 ^ k1 ^ 0x1BD11BDAu;
    x0 += k0; x1 += k1;
#define TF_RND(r) { x0 += x1; x1 = rotl32(x1, r); x1 ^= x0; }
    TF_RND(13) TF_RND(15) TF_RND(26) TF_RND(6)
    x0 += k1; x1 += ks2 + 1u;
    TF_RND(17) TF_RND(29) TF_RND(16) TF_RND(24)
    x0 += ks2; x1 += k0 + 2u;
    TF_RND(13) TF_RND(15) TF_RND(26) TF_RND(6)
    x0 += k0; x1 += k1 + 3u;
    TF_RND(17) TF_RND(29) TF_RND(16) TF_RND(24)
    x0 += k1; x1 += ks2 + 4u;
    TF_RND(13) TF_RND(15) TF_RND(26) TF_RND(6)
    x0 += ks2; x1 += k0 + 5u;
#undef TF_RND
    o0 = x0; o1 = x1;
}

__device__ __forceinline__ unsigned int tf_bits32(unsigned int k0, unsigned int k1,
                                                  unsigned int idx) {
    unsigned int o0, o1;
    threefry2x32(k0, k1, 0u, idx, o0, o1);
    return o0 ^ o1;
}

__device__ __forceinline__ float gumbel_from_bits(unsigned int bits) {
    float f = __uint_as_float((bits >> 9) | 0x3f800000u) - 1.0f;
    float u = f + TINYF;
    u = fmaxf(TINYF, u);
    return -logf(-logf(u));
}

// ---------------- two-level grid barrier ----------------
template <int NBLK>
__device__ __forceinline__ void gsync(unsigned int& gen, int bid) {
    __syncthreads();
    if (threadIdx.x == 0) {
        __threadfence();
        unsigned int t = atomicAdd(&g_cnt1[(bid & 7) * 32], 1u);
        bool released = false;
        if (t == (unsigned int)(NBLK / 8 - 1)) {
            unsigned int r = atomicAdd(&g_cntr, 1u);
            if (r == 7u) {
#pragma unroll
                for (int i = 0; i < 8; i++) atomicExch(&g_cnt1[i * 32], 0u);
                atomicExch(&g_cntr, 0u);
                __threadfence();
                atomicExch(&g_gen, gen + 1);
                released = true;
            }
        }
        if (!released) {
            volatile unsigned int* p = &g_gen;
            while ((int)(*p - (gen + 1)) < 0) { }
            __threadfence();
        }
    }
    gen++;
    __syncthreads();
}

// ---------------- worker GEMM tile: C[128 x 64] = A[M][K] @ W[N][K]^T ----------------
__device__ void wtile(const float* __restrict__ A, const float* __restrict__ W,
                      float* __restrict__ C, int K, int N, int bm, int bn,
                      int transOut, int tid, float (*As)[132], float (*Bs)[68]) {
    int tx = tid & 15, ty = tid >> 4;
    float acc[8][4];
#pragma unroll
    for (int i = 0; i < 8; i++)
#pragma unroll
        for (int j = 0; j < 4; j++) acc[i][j] = 0.0f;

    for (int k0 = 0; k0 < K; k0 += 16) {
#pragma unroll
        for (int l = 0; l < 2; l++) {
            int slot = tid + l * 256;
            int r = slot >> 2, c4 = slot & 3;
            float4 va = *reinterpret_cast<const float4*>(&A[(size_t)(bm + r) * K + k0 + c4 * 4]);
            As[c4 * 4 + 0][r] = va.x;
            As[c4 * 4 + 1][r] = va.y;
            As[c4 * 4 + 2][r] = va.z;
            As[c4 * 4 + 3][r] = va.w;
        }
        {
            int r = tid >> 2, c4 = tid & 3;
            float4 vb = *reinterpret_cast<const float4*>(&W[(size_t)(bn + r) * K + k0 + c4 * 4]);
            Bs[c4 * 4 + 0][r] = vb.x;
            Bs[c4 * 4 + 1][r] = vb.y;
            Bs[c4 * 4 + 2][r] = vb.z;
            Bs[c4 * 4 + 3][r] = vb.w;
        }
        __syncthreads();
#pragma unroll
        for (int kk = 0; kk < 16; kk++) {
            float4 a0 = *reinterpret_cast<const float4*>(&As[kk][ty * 8]);
            float4 a1 = *reinterpret_cast<const float4*>(&As[kk][ty * 8 + 4]);
            float4 b0 = *reinterpret_cast<const float4*>(&Bs[kk][tx * 4]);
            float a[8] = {a0.x, a0.y, a0.z, a0.w, a1.x, a1.y, a1.z, a1.w};
            float b[4] = {b0.x, b0.y, b0.z, b0.w};
#pragma unroll
            for (int i = 0; i < 8; i++)
#pragma unroll
                for (int j = 0; j < 4; j++)
                    acc[i][j] = fmaf(a[i], b[j], acc[i][j]);
        }
        __syncthreads();
    }
#pragma unroll
    for (int i = 0; i < 8; i++) {
        int m = bm + ty * 8 + i;
        size_t row = transOut ? ((size_t)(m & (Bq - 1)) * Sq + (m >> 8)) : (size_t)m;
        *reinterpret_cast<float4*>(&C[row * N + bn + tx * 4]) =
            make_float4(acc[i][0], acc[i][1], acc[i][2], acc[i][3]);
    }
}

// ---------------- encoder lstm phase (128 blocks, 32b x 16h tiles) ----------------
__device__ __forceinline__ void lstm_phase_enc(
    int bid, int tid,
    const float* __restrict__ hin, float* __restrict__ hout,
    const float* __restrict__ Whh, const float* __restrict__ bih,
    const float* __restrict__ bhh,
    const float* __restrict__ xg,
    float* __restrict__ encout,
    float (*As)[34], float (*Bs)[68])
{
    int tb = bid >> 4, th = bid & 15;
    int bm = tb * 32, h0 = th * 16;
    int tx = tid & 15, ty = tid >> 4;
    float acc[2][4];
#pragma unroll
    for (int i = 0; i < 2; i++)
#pragma unroll
        for (int g = 0; g < 4; g++) acc[i][g] = 0.0f;

    for (int k0 = 0; k0 < Hq; k0 += 16) {
#pragma unroll
        for (int l = 0; l < 2; l++) {
            int idx = tid + l * 256;
            int m = idx >> 4, kk = idx & 15;
            As[kk][m] = hin[(bm + m) * Hq + k0 + kk];
        }
#pragma unroll
        for (int l = 0; l < 4; l++) {
            int idx = tid + l * 256;
            int c = idx >> 4, kk = idx & 15;
            int h = c >> 2, g = c & 3;
            Bs[kk][c] = Whh[(g * Hq + h0 + h) * Hq + k0 + kk];
        }
        __syncthreads();
#pragma unroll
        for (int kk = 0; kk < 16; kk++) {
            float2 a2 = *reinterpret_cast<const float2*>(&As[kk][ty * 2]);
            float4 b4 = *reinterpret_cast<const float4*>(&Bs[kk][tx * 4]);
            acc[0][0] = fmaf(a2.x, b4.x, acc[0][0]);
            acc[0][1] = fmaf(a2.x, b4.y, acc[0][1]);
            acc[0][2] = fmaf(a2.x, b4.z, acc[0][2]);
            acc[0][3] = fmaf(a2.x, b4.w, acc[0][3]);
            acc[1][0] = fmaf(a2.y, b4.x, acc[1][0]);
            acc[1][1] = fmaf(a2.y, b4.y, acc[1][1]);
            acc[1][2] = fmaf(a2.y, b4.z, acc[1][2]);
            acc[1][3] = fmaf(a2.y, b4.w, acc[1][3]);
        }
        __syncthreads();
    }

    int h = h0 + tx;
#pragma unroll
    for (int i = 0; i < 2; i++) {
        int b = bm + ty * 2 + i;
        size_t xrow = (size_t)b * G4;
        float gi = acc[i][0] + xg[xrow + h]          + bih[h]          + bhh[h];
        float gf = acc[i][1] + xg[xrow + Hq + h]     + bih[Hq + h]     + bhh[Hq + h];
        float gg = acc[i][2] + xg[xrow + 2*Hq + h]   + bih[2*Hq + h]   + bhh[2*Hq + h];
        float go = acc[i][3] + xg[xrow + 3*Hq + h]   + bih[3*Hq + h]   + bhh[3*Hq + h];
        int idx = b * Hq + h;
        float cc = d_c[idx];
        float cn = xsigmoid(gf) * cc + xsigmoid(gi) * xtanh(gg);
        float hn = xsigmoid(go) * xtanh(cn);
        d_c[idx] = cn;
        hout[idx] = hn;
        encout[idx] = hn;
    }
}

// ---------------- fused encoder + precompute workers (256 blocks, 2 CTA/SM) ----------------
__global__ __launch_bounds__(256, 2) void k_encfuse(const float* __restrict__ Whh,
                                                    const float* __restrict__ bih,
                                                    const float* __restrict__ bhh,
                                                    const float* __restrict__ Wih_enc,
                                                    const float* __restrict__ Wih_dec,
                                                    const float* __restrict__ Wref) {
    __shared__ float EA[16][34];
    __shared__ float SA[16][132];
    __shared__ float SB[16][68];
    __shared__ unsigned int s_gen0;
    int tid = threadIdx.x, bid = blockIdx.x;

    if (bid < NB_ENC) {
        if (tid == 0) s_gen0 = atomicAdd(&g_gen, 0u);
        __syncthreads();
        unsigned int gen = s_gen0;
        for (int s = 0; s < Sq; s++) {
            if (tid == 0) {
                volatile int* c = d_xgcnt;
                while (c[s] < 32) { }
            }
            __syncthreads();
            const float* hin = d_hbuf + (s & 1) * (Bq * Hq);
            float* hout = d_hbuf + ((s & 1) ^ 1) * (Bq * Hq);
            lstm_phase_enc(bid, tid, hin, hout, Whh, bih, bhh,
                           d_XgEnc + (size_t)s * Bq * G4,
                           d_encout + (size_t)s * Bq * Hq, EA, SB);
            gsync<NB_ENC>(gen, bid);
            if (bid == 0 && tid == 0) atomicExch(&g_enc_done, (unsigned int)(s + 1));
        }
    } else {
        int wd = bid - NB_ENC;
        for (int j = wd; j < 16384; j += NW) {
            int bmT = j >> 4, bnT = j & 15;
            wtile(d_emb, Wih_enc, d_XgEnc, Eq, G4, bmT * 128, bnT * 64, 0, tid, SA, SB);
            __syncthreads();
            if (tid == 0) { __threadfence(); atomicAdd(&d_xgcnt[bmT >> 1], 1); }
        }
        for (int j = wd; j < 16384; j += NW) {
            int bmT = j >> 4, bnT = j & 15;
            wtile(d_emb, Wih_dec, d_Dg, Eq, G4, bmT * 128, bnT * 64, 0, tid, SA, SB);
            __syncthreads();
        }
        {
            size_t total = (size_t)(Sq - 1) * Bq * Sq;
            for (size_t g = (size_t)(wd * 256 + tid); g < total; g += (size_t)NW * 256) {
                int t = (int)(g >> 17);
                unsigned int r = (unsigned int)(g & 131071u);
                d_gum[g] = gumbel_from_bits(tf_bits32(d_keys[2 * t], d_keys[2 * t + 1], r));
            }
        }
        for (int j = wd; j < 4096; j += NW) {
            int bmT = j >> 2, bnT = j & 3;
            unsigned int sneed = (unsigned int)((bmT * 128 + 127) >> 8) + 1u;
            if (tid == 0) {
                volatile unsigned int* p = &g_enc_done;
                while (*p < sneed) { }
            }
            __syncthreads();
            wtile(d_encout, Wref, d_refproj, Hq, Hq, bmT * 128, bnT * 64, 1, tid, SA, SB);
            __syncthreads();
        }
    }
}

// ---------------- persistent decoder: 256 blocks, 2 CTA/SM, dynamic smem ----------------
// dyn layout (floats): WhhS 16384 | WqS 4096 | AsS 4352 | qs 256 | vsm 256 | ls 512 |
//                      redf 8 | redm 8 | redi 8(int) | sch 1 | sg0 1
#define DYN_WHH 0
#define DYN_WQ 16384
#define DYN_AS 20480
#define DYN_QS 24832
#define DYN_VS 25088
#define DYN_LS 25344
#define DYN_RF 25856
#define DYN_RM 25864
#define DYN_RI 25872
#define DYN_CH 25880
#define DYN_G0 25881
#define DYN_TOTAL 25882
#define DEC_DSMEM (DYN_TOTAL * 4 + 56)

__global__ __launch_bounds__(256, 2) void k_decoder(const float* __restrict__ Whh,
                                                    const float* __restrict__ bih,
                                                    const float* __restrict__ bhh,
                                                    const float* __restrict__ Wq,
                                                    const float* __restrict__ vvec) {
    extern __shared__ float dyn[];
    float* WhhS = dyn + DYN_WHH;
    float* WqS  = dyn + DYN_WQ;
    float* AsS  = dyn + DYN_AS;
    float* qs   = dyn + DYN_QS;
    float* vsm  = dyn + DYN_VS;
    float* ls   = dyn + DYN_LS;
    float* redf = dyn + DYN_RF;
    float* redm = dyn + DYN_RM;
    int*   redi = (int*)(dyn + DYN_RI);
    int*   sch  = (int*)(dyn + DYN_CH);
    unsigned int* sg0 = (unsigned int*)(dyn + DYN_G0);

    int tid = threadIdx.x, bid = blockIdx.x;
    if (tid == 0) *sg0 = atomicAdd(&g_gen, 0u);
    vsm[tid] = vvec[tid];

    int tbA = bid >> 4, thA = bid & 15;
    int bmA = tbA * 16, h0A = thA * 16;
    int txA = tid & 15, tyA = tid >> 4;
    int w = tid >> 5, lane = tid & 31;
    int b = bid;

    // persistent Whh slice: WhhS[k*64 + (h*4+g)] = Whh[(g*256 + h0A + h)*256 + k]
    for (int i = tid; i < 16384; i += 256) {
        int c = i >> 8, k = i & 255;
        int h = c >> 2, g = c & 3;
        WhhS[k * 64 + c] = Whh[(g * Hq + h0A + h) * Hq + k];
    }
    // persistent Wq k-slice: WqS[kk*256 + j] = Wq[j*256 + h0A + kk]
    for (int i = tid; i < 4096; i += 256) {
        int jj = i >> 4, kk = i & 15;
        WqS[kk * 256 + jj] = Wq[jj * Hq + h0A + kk];
    }
    __syncthreads();
    unsigned int gen = *sg0;

    const float4* vs4 = (const float4*)vsm;
    float4 v0 = vs4[lane], v1 = vs4[lane + 32];
    ull vp0 = pk2(v0.x, v0.y), vp1 = pk2(v0.z, v0.w);
    ull vp2 = pk2(v1.x, v1.y), vp3 = pk2(v1.z, v1.w);

    for (int t = 0; t < Sq - 1; t++) {
        const float* hin = d_hbuf + (t & 1) * (Bq * Hq);
        float* hout = d_hbuf + ((t & 1) ^ 1) * (Bq * Hq);

        // ---- Phase A: gates GEMM (smem-resident weights) + cell + partial q ----
        {
#pragma unroll
            for (int l = 0; l < 16; l++)
                AsS[tid * 17 + l] = hin[(bmA + l) * Hq + tid];
            __syncthreads();
            float acc0 = 0.0f, acc1 = 0.0f, acc2 = 0.0f, acc3 = 0.0f;
#pragma unroll 16
            for (int k = 0; k < Hq; k++) {
                float a = AsS[k * 17 + tyA];
                float4 b4 = *(const float4*)&WhhS[k * 64 + txA * 4];
                acc0 = fmaf(a, b4.x, acc0);
                acc1 = fmaf(a, b4.y, acc1);
                acc2 = fmaf(a, b4.z, acc2);
                acc3 = fmaf(a, b4.w, acc3);
            }
            int bb = bmA + tyA, h = h0A + txA;
            size_t xrow = ((size_t)d_chosen[bb] * Bq + bb) * G4;
            float gi = acc0 + d_Dg[xrow + h]          + bih[h]          + bhh[h];
            float gf = acc1 + d_Dg[xrow + Hq + h]     + bih[Hq + h]     + bhh[Hq + h];
            float gg = acc2 + d_Dg[xrow + 2*Hq + h]   + bih[2*Hq + h]   + bhh[2*Hq + h];
            float go = acc3 + d_Dg[xrow + 3*Hq + h]   + bih[3*Hq + h]   + bhh[3*Hq + h];
            int idx = bb * Hq + h;
            float cc = d_c[idx];
            float cn = xsigmoid(gf) * cc + xsigmoid(gi) * xtanh(gg);
            float hn = xsigmoid(go) * xtanh(cn);
            d_c[idx] = cn;
            hout[idx] = hn;
            __syncthreads();
            AsS[tyA * 16 + txA] = hn;   // hnS[b_local*16 + k_local]
            __syncthreads();
            // partial q over this block's k-slice: ascending kk
            const float* hrow = &AsS[tyA * 16];
            float* qp = &d_qpart[((size_t)(bmA + tyA) * 16 + thA) * Hq];
#pragma unroll
            for (int jj = 0; jj < 16; jj++) {
                int j = jj * 16 + txA;
                float s = 0.0f;
#pragma unroll
                for (int kk = 0; kk < 16; kk++)
                    s = fmaf(hrow[kk], WqS[kk * 256 + j], s);
                qp[j] = s;
            }
        }
        gsync<NB_DEC>(gen, bid);

        // ---- Phase C: q-sum + attention logits + gumbel argmax + log-softmax ----
        {
            int n = Sq - 1 - t;
            const float* gum = d_gum + ((size_t)t * Bq + b) * Sq;
            float qv = 0.0f;
            const float* qp = &d_qpart[(size_t)b * 16 * Hq];
#pragma unroll
            for (int th = 0; th < 16; th++)
                qv += qp[th * Hq + tid];
            qs[tid] = qv;
            ls[tid] = MASKVAL;
            ls[tid + 256] = MASKVAL;
            float g0 = gum[tid], g1 = gum[tid + 256];
            __syncthreads();

            const float4* qs4 = (const float4*)qs;
            float4 q0 = qs4[lane], q1 = qs4[lane + 32];
            const int* lst = d_plist + b * Sq;
            const float* rbase = d_refproj + (size_t)b * Sq * Hq;

            for (int k0 = w * 4; k0 < n; k0 += 32) {
                int4 sxv = *reinterpret_cast<const int4*>(lst + k0);
                int sx[4] = {sxv.x, sxv.y, sxv.z, sxv.w};
                float4 ra[4], rb[4];
#pragma unroll
                for (int j = 0; j < 4; j++) {
                    const float4* p = reinterpret_cast<const float4*>(
                        rbase + (size_t)sx[j] * Hq);
                    ra[j] = p[lane];
                    rb[j] = p[lane + 32];
                }
                float sums[4];
#pragma unroll
                for (int j = 0; j < 4; j++) {
                    ull s2 = 0ULL;
                    ull T;
                    T = xtanh2pk(clamp_pack(q0.x + ra[j].x, q0.y + ra[j].y));
                    s2 = fma2(vp0, T, s2);
                    T = xtanh2pk(clamp_pack(q0.z + ra[j].z, q0.w + ra[j].w));
                    s2 = fma2(vp1, T, s2);
                    T = xtanh2pk(clamp_pack(q1.x + rb[j].x, q1.y + rb[j].y));
                    s2 = fma2(vp2, T, s2);
                    T = xtanh2pk(clamp_pack(q1.z + rb[j].z, q1.w + rb[j].w));
                    s2 = fma2(vp3, T, s2);
                    float lo, hi;
                    upk2(s2, lo, hi);
                    sums[j] = lo + hi;
                }
#pragma unroll
                for (int off = 16; off > 0; off >>= 1) {
                    sums[0] += __shfl_down_sync(0xffffffffu, sums[0], off);
                    sums[1] += __shfl_down_sync(0xffffffffu, sums[1], off);
                    sums[2] += __shfl_down_sync(0xffffffffu, sums[2], off);
                    sums[3] += __shfl_down_sync(0xffffffffu, sums[3], off);
                }
                if (lane == 0) {
#pragma unroll
                    for (int j = 0; j < 4; j++)
                        if (k0 + j < n) ls[sx[j]] = sums[j];
                }
            }
            __syncthreads();

            float l0 = ls[tid], l1 = ls[tid + 256];
            float o0 = (l0 == MASKVAL) ? -1e30f : l0 + g0;
            float o1 = (l1 == MASKVAL) ? -1e30f : l1 + g1;

            // merged argmax + logit-max reduction
            float bv; int bi;
            if (o0 >= o1) { bv = o0; bi = tid; }
            else { bv = o1; bi = tid + 256; }
            float mx = fmaxf(l0, l1);
#pragma unroll
            for (int off = 16; off > 0; off >>= 1) {
                float ov = __shfl_down_sync(0xffffffffu, bv, off);
                int oi = __shfl_down_sync(0xffffffffu, bi, off);
                float om = __shfl_down_sync(0xffffffffu, mx, off);
                if (ov > bv || (ov == bv && oi < bi)) { bv = ov; bi = oi; }
                mx = fmaxf(mx, om);
            }
            if (lane == 0) { redf[w] = bv; redi[w] = bi; redm[w] = mx; }
            __syncthreads();
            if (w == 0) {
                float v8 = (lane < 8) ? redf[lane] : -1e38f;
                int i8 = (lane < 8) ? redi[lane] : 0x7fffffff;
                float m8 = (lane < 8) ? redm[lane] : -1e38f;
#pragma unroll
                for (int off = 4; off > 0; off >>= 1) {
                    float ov = __shfl_down_sync(0xffffffffu, v8, off);
                    int oi = __shfl_down_sync(0xffffffffu, i8, off);
                    float om = __shfl_down_sync(0xffffffffu, m8, off);
                    if (ov > v8 || (ov == v8 && oi < i8)) { v8 = ov; i8 = oi; }
                    m8 = fmaxf(m8, om);
                }
                if (lane == 0) { *sch = i8; redm[0] = m8; }
            }
            __syncthreads();
            int ch = *sch;
            float m = redm[0];

            float e = expf(l0 - m) + expf(l1 - m);
#pragma unroll
            for (int off = 16; off > 0; off >>= 1)
                e += __shfl_down_sync(0xffffffffu, e, off);
            if (lane == 0) redf[w] = e;
            __syncthreads();
            if (w == 0) {
                float s8 = (lane < 8) ? redf[lane] : 0.0f;
#pragma unroll
                for (int off = 4; off > 0; off >>= 1)
                    s8 += __shfl_down_sync(0xffffffffu, s8, off);
                if (lane == 0) {
                    float lp = (ls[ch] - m) - logf(s8);
                    d_lp[(size_t)t * Bq + b] = lp;
                    d_idx[(size_t)t * Bq + b] = ch;
                    d_chosen[b] = ch;
                    int base = b * Sq;
                    int kk = d_ppos[base + ch];
                    int sl = d_plist[base + n - 1];
                    d_plist[base + kk] = sl;
                    d_ppos[base + sl] = kk;
                    d_plist[base + n - 1] = ch;
                }
            }
        }
        gsync<NB_DEC>(gen, bid);
    }
}

// ---------------- init ----------------
__global__ __launch_bounds__(256) void k_init() {
    int i = blockIdx.x * 256 + threadIdx.x;
    if (i < 2 * Bq * Hq) d_hbuf[i] = 0.0f;
    if (i < Bq * Hq) d_c[i] = 0.0f;
    if (i < Bq * Sq) {
        int bb = i >> 9, s = i & (Sq - 1);
        if (s > 0) {
            d_plist[bb * Sq + (s - 1)] = s;
            d_ppos[bb * Sq + s] = s - 1;
        } else {
            d_plist[bb * Sq + (Sq - 1)] = 0;
            d_ppos[bb * Sq] = -1;
        }
    }
    if (i < Bq) d_chosen[i] = 0;
    if (i < Sq) d_xgcnt[i] = 0;
    if (i < 8 * 32) g_cnt1[i] = 0u;
    if (i == 0) { g_enc_done = 0u; g_cntr = 0u; }
    if (i < (Sq - 1)) {
        unsigned int o0, o1;
        threefry2x32(0u, 1u, 0u, (unsigned int)i, o0, o1);
        d_keys[2 * i] = o0;
        d_keys[2 * i + 1] = o1;
    }
}

__global__ __launch_bounds__(256) void k_embed(const float* __restrict__ inputs,
                                               const float* __restrict__ W_embed) {
    int i = blockIdx.x * 256 + threadIdx.x;
    int e = i & (Eq - 1);
    int b = (i >> 8) & (Bq - 1);
    int s = i >> 16;
    const float* inp = inputs + ((size_t)b * Sq + s) * 2;
    d_emb[i] = fmaf(inp[1], W_embed[Eq + e], inp[0] * W_embed[e]);
}

__global__ __launch_bounds__(256) void k_final(float* __restrict__ out) {
    int i = blockIdx.x * 256 + threadIdx.x;
    const int NLP = Bq * (Sq - 1);
    if (i < NLP) {
        int b = i / (Sq - 1), t = i % (Sq - 1);
        out[i] = d_lp[(size_t)t * Bq + b];
    } else if (i < NLP + Bq * Sq) {
        int j = i - NLP;
        int b = j >> 9, s = j & (Sq - 1);
        out[i] = (s == 0) ? 0.0f : (float)d_idx[(size_t)(s - 1) * Bq + b];
    }
}

// ---------------- host ----------------
extern "C" void kernel_launch(void* const* d_in, const int* in_sizes, int n_in,
                              void* d_out, int out_size) {
    const float* inputs   = (const float*)d_in[0];
    const float* W_embed  = (const float*)d_in[1];
    const float* enc_Wih  = (const float*)d_in[2];
    const float* enc_Whh  = (const float*)d_in[3];
    const float* enc_bih  = (const float*)d_in[4];
    const float* enc_bhh  = (const float*)d_in[5];
    const float* dec_Wih  = (const float*)d_in[6];
    const float* dec_Whh  = (const float*)d_in[7];
    const float* dec_bih  = (const float*)d_in[8];
    const float* dec_bhh  = (const float*)d_in[9];
    const float* Wq       = (const float*)d_in[10];
    const float* Wref     = (const float*)d_in[11];
    const float* v        = (const float*)d_in[12];

    cudaFuncSetAttribute(k_decoder, cudaFuncAttributeMaxDynamicSharedMemorySize,
                         DEC_DSMEM);

    k_init<<<512, 256>>>();
    k_embed<<<(Sq * Bq * Eq) / 256, 256>>>(inputs, W_embed);

    // fused: encoder (blocks 0-127) + precompute workers (blocks 128-255)
    k_encfuse<<<NB_ENC + NW, 256>>>(enc_Whh, enc_bih, enc_bhh,
                                    enc_Wih, dec_Wih, Wref);

    k_decoder<<<NB_DEC, 256, DEC_DSMEM>>>(dec_Whh, dec_bih, dec_bhh, Wq, v);

    k_final<<<(Bq * (Sq - 1) + Bq * Sq + 255) / 256, 256>>>((float*)d_out);
}

// round 12
// speedup vs baseline: 1.3310x; 1.3310x over previous
#include <cuda_runtime.h>
#include <cstdint>

#define Bq 256
#define Sq 512
#define Eq 256
#define Hq 256
#define G4 1024
#define NB_ENC 128
#define NW 128
#define NB_DEC 256
#define MASKVAL -100000.0f
#define TINYF 1.17549435e-38f
#define CLV 7.90531110763549805f

typedef unsigned long long ull;

// ---------------- device globals (static scratch) ----------------
__device__ float d_emb[(size_t)Sq * Bq * Eq];        // [s][b][e]
__device__ float d_XgEnc[(size_t)Sq * Bq * G4];      // [s][b][j]
__device__ float d_Dg[(size_t)Sq * Bq * G4];         // [s][b][j]
__device__ float d_encout[(size_t)Sq * Bq * Hq];     // [s][b][h]
__device__ float d_refproj[(size_t)Bq * Sq * Hq];    // [b][s][h]
__device__ float d_gum[(size_t)(Sq - 1) * Bq * Sq];  // [t][b][s]
__device__ float d_WqT[Hq * Hq];                     // [k][h]
__device__ float d_hbuf[2 * Bq * Hq];
__device__ float d_c[Bq * Hq];
__device__ int d_plist[Bq * Sq];
__device__ int d_ppos[Bq * Sq];
__device__ int d_chosen[Bq];
__device__ unsigned int d_keys[(Sq - 1) * 2];
__device__ float d_lp[(Sq - 1) * Bq];
__device__ int d_idx[(Sq - 1) * Bq];
__device__ int d_xgcnt[Sq];
__device__ unsigned int g_enc_done = 0;
__device__ unsigned int g_cnt1[8 * 32];              // padded sub-counters (128B apart)
__device__ unsigned int g_cntr = 0;
__device__ unsigned int g_gen = 0;

// ---------------- f32x2 packed helpers ----------------
__device__ __forceinline__ ull pk2(float lo, float hi) {
    ull r;
    asm("mov.b64 %0, {%1, %2};" : "=l"(r) : "f"(lo), "f"(hi));
    return r;
}
__device__ __forceinline__ void upk2(ull v, float& lo, float& hi) {
    asm("mov.b64 {%0, %1}, %2;" : "=f"(lo), "=f"(hi) : "l"(v));
}
__device__ __forceinline__ ull fma2(ull a, ull b, ull c) {
    ull d;
    asm("fma.rn.f32x2 %0, %1, %2, %3;" : "=l"(d) : "l"(a), "l"(b), "l"(c));
    return d;
}
__device__ __forceinline__ ull mul2(ull a, ull b) {
    ull d;
    asm("mul.rn.f32x2 %0, %1, %2;" : "=l"(d) : "l"(a), "l"(b));
    return d;
}
__device__ __forceinline__ ull pk1(float c) { return pk2(c, c); }

// ---------------- math helpers ----------------
__device__ __forceinline__ float xtanh(float x) {
    float ax = fabsf(x);
    float xc = fminf(fmaxf(x, -CLV), CLV);
    float x2 = xc * xc;
    float p = -2.76076847742355e-16f;
    p = fmaf(p, x2, 2.00018790482477e-13f);
    p = fmaf(p, x2, -8.60467152213735e-11f);
    p = fmaf(p, x2, 5.12229709037114e-08f);
    p = fmaf(p, x2, 1.48572235717979e-05f);
    p = fmaf(p, x2, 6.37261928875436e-04f);
    p = fmaf(p, x2, 4.89352455891786e-03f);
    float q = 1.19825839466702e-06f;
    q = fmaf(q, x2, 1.18534705686654e-04f);
    q = fmaf(q, x2, 2.26843463243900e-03f);
    q = fmaf(q, x2, 4.89352518554385e-03f);
    float t = (xc * p) / q;
    return (ax < 0.0004f) ? x : t;
}

__device__ __forceinline__ ull xtanh2pk(ull X) {
    ull x2 = mul2(X, X);
    ull p = pk1(-2.76076847742355e-16f);
    p = fma2(p, x2, pk1(2.00018790482477e-13f));
    p = fma2(p, x2, pk1(-8.60467152213735e-11f));
    p = fma2(p, x2, pk1(5.12229709037114e-08f));
    p = fma2(p, x2, pk1(1.48572235717979e-05f));
    p = fma2(p, x2, pk1(6.37261928875436e-04f));
    p = fma2(p, x2, pk1(4.89352455891786e-03f));
    ull q = pk1(1.19825839466702e-06f);
    q = fma2(q, x2, pk1(1.18534705686654e-04f));
    q = fma2(q, x2, pk1(2.26843463243900e-03f));
    q = fma2(q, x2, pk1(4.89352518554385e-03f));
    ull num = mul2(X, p);
    float qa, qb;
    upk2(q, qa, qb);
    float ra, rb;
    asm("rcp.approx.f32 %0, %1;" : "=f"(ra) : "f"(qa));
    asm("rcp.approx.f32 %0, %1;" : "=f"(rb) : "f"(qb));
    ull rr = pk2(ra, rb);
    ull nq = q ^ 0x8000000080000000ULL;
    ull e = fma2(nq, rr, pk1(1.0f));
    rr = fma2(e, rr, rr);
    return mul2(num, rr);
}

__device__ __forceinline__ ull clamp_pack(float a, float b) {
    float ca = fminf(fmaxf(a, -CLV), CLV);
    float cb = fminf(fmaxf(b, -CLV), CLV);
    return pk2(ca, cb);
}

__device__ __forceinline__ float xsigmoid(float x) {
    return 1.0f / (1.0f + expf(-x));
}

__device__ __forceinline__ unsigned int rotl32(unsigned int v, int r) {
    return (v << r) | (v >> (32 - r));
}

__device__ __forceinline__ void threefry2x32(unsigned int k0, unsigned int k1,
                                             unsigned int x0, unsigned int x1,
                                             unsigned int& o0, unsigned int& o1) {
    unsigned int ks2 = k0 ^ k1 ^ 0x1BD11BDAu;
    x0 += k0; x1 += k1;
#define TF_RND(r) { x0 += x1; x1 = rotl32(x1, r); x1 ^= x0; }
    TF_RND(13) TF_RND(15) TF_RND(26) TF_RND(6)
    x0 += k1; x1 += ks2 + 1u;
    TF_RND(17) TF_RND(29) TF_RND(16) TF_RND(24)
    x0 += ks2; x1 += k0 + 2u;
    TF_RND(13) TF_RND(15) TF_RND(26) TF_RND(6)
    x0 += k0; x1 += k1 + 3u;
    TF_RND(17) TF_RND(29) TF_RND(16) TF_RND(24)
    x0 += k1; x1 += ks2 + 4u;
    TF_RND(13) TF_RND(15) TF_RND(26) TF_RND(6)
    x0 += ks2; x1 += k0 + 5u;
#undef TF_RND
    o0 = x0; o1 = x1;
}

__device__ __forceinline__ unsigned int tf_bits32(unsigned int k0, unsigned int k1,
                                                  unsigned int idx) {
    unsigned int o0, o1;
    threefry2x32(k0, k1, 0u, idx, o0, o1);
    return o0 ^ o1;
}

__device__ __forceinline__ float gumbel_from_bits(unsigned int bits) {
    float f = __uint_as_float((bits >> 9) | 0x3f800000u) - 1.0f;
    float u = f + TINYF;
    u = fmaxf(TINYF, u);
    return -logf(-logf(u));
}

// ---------------- two-level grid barrier (8 padded sub-counters + root) ----------------
template <int NBLK>
__device__ __forceinline__ void gsync(unsigned int& gen, int bid) {
    __syncthreads();
    if (threadIdx.x == 0) {
        __threadfence();
        unsigned int t = atomicAdd(&g_cnt1[(bid & 7) * 32], 1u);
        bool released = false;
        if (t == (unsigned int)(NBLK / 8 - 1)) {
            unsigned int r = atomicAdd(&g_cntr, 1u);
            if (r == 7u) {
#pragma unroll
                for (int i = 0; i < 8; i++) atomicExch(&g_cnt1[i * 32], 0u);
                atomicExch(&g_cntr, 0u);
                __threadfence();
                atomicExch(&g_gen, gen + 1);
                released = true;
            }
        }
        if (!released) {
            volatile unsigned int* p = &g_gen;
            while ((int)(*p - (gen + 1)) < 0) { }
            __threadfence();
        }
    }
    gen++;
    __syncthreads();
}

// ---------------- worker GEMM tile: C[128 x 64] = A[M][K] @ W[N][K]^T ----------------
__device__ void wtile(const float* __restrict__ A, const float* __restrict__ W,
                      float* __restrict__ C, int K, int N, int bm, int bn,
                      int transOut, int tid, float (*As)[132], float (*Bs)[68]) {
    int tx = tid & 15, ty = tid >> 4;
    float acc[8][4];
#pragma unroll
    for (int i = 0; i < 8; i++)
#pragma unroll
        for (int j = 0; j < 4; j++) acc[i][j] = 0.0f;

    for (int k0 = 0; k0 < K; k0 += 16) {
#pragma unroll
        for (int l = 0; l < 2; l++) {
            int slot = tid + l * 256;
            int r = slot >> 2, c4 = slot & 3;
            float4 va = *reinterpret_cast<const float4*>(&A[(size_t)(bm + r) * K + k0 + c4 * 4]);
            As[c4 * 4 + 0][r] = va.x;
            As[c4 * 4 + 1][r] = va.y;
            As[c4 * 4 + 2][r] = va.z;
            As[c4 * 4 + 3][r] = va.w;
        }
        {
            int r = tid >> 2, c4 = tid & 3;
            float4 vb = *reinterpret_cast<const float4*>(&W[(size_t)(bn + r) * K + k0 + c4 * 4]);
            Bs[c4 * 4 + 0][r] = vb.x;
            Bs[c4 * 4 + 1][r] = vb.y;
            Bs[c4 * 4 + 2][r] = vb.z;
            Bs[c4 * 4 + 3][r] = vb.w;
        }
        __syncthreads();
#pragma unroll
        for (int kk = 0; kk < 16; kk++) {
            float4 a0 = *reinterpret_cast<const float4*>(&As[kk][ty * 8]);
            float4 a1 = *reinterpret_cast<const float4*>(&As[kk][ty * 8 + 4]);
            float4 b0 = *reinterpret_cast<const float4*>(&Bs[kk][tx * 4]);
            float a[8] = {a0.x, a0.y, a0.z, a0.w, a1.x, a1.y, a1.z, a1.w};
            float b[4] = {b0.x, b0.y, b0.z, b0.w};
#pragma unroll
            for (int i = 0; i < 8; i++)
#pragma unroll
                for (int j = 0; j < 4; j++)
                    acc[i][j] = fmaf(a[i], b[j], acc[i][j]);
        }
        __syncthreads();
    }
#pragma unroll
    for (int i = 0; i < 8; i++) {
        int m = bm + ty * 8 + i;
        size_t row = transOut ? ((size_t)(m & (Bq - 1)) * Sq + (m >> 8)) : (size_t)m;
        *reinterpret_cast<float4*>(&C[row * N + bn + tx * 4]) =
            make_float4(acc[i][0], acc[i][1], acc[i][2], acc[i][3]);
    }
}

// ---------------- encoder lstm phase (128 blocks, 32b x 16h tiles) ----------------
__device__ __forceinline__ void lstm_phase_enc(
    int bid, int tid,
    const float* __restrict__ hin, float* __restrict__ hout,
    const float* __restrict__ Whh, const float* __restrict__ bih,
    const float* __restrict__ bhh,
    const float* __restrict__ xg,
    float* __restrict__ encout,
    float (*As)[34], float (*Bs)[68])
{
    int tb = bid >> 4, th = bid & 15;
    int bm = tb * 32, h0 = th * 16;
    int tx = tid & 15, ty = tid >> 4;
    float acc[2][4];
#pragma unroll
    for (int i = 0; i < 2; i++)
#pragma unroll
        for (int g = 0; g < 4; g++) acc[i][g] = 0.0f;

    for (int k0 = 0; k0 < Hq; k0 += 16) {
#pragma unroll
        for (int l = 0; l < 2; l++) {
            int idx = tid + l * 256;
            int m = idx >> 4, kk = idx & 15;
            As[kk][m] = hin[(bm + m) * Hq + k0 + kk];
        }
#pragma unroll
        for (int l = 0; l < 4; l++) {
            int idx = tid + l * 256;
            int c = idx >> 4, kk = idx & 15;
            int h = c >> 2, g = c & 3;
            Bs[kk][c] = Whh[(g * Hq + h0 + h) * Hq + k0 + kk];
        }
        __syncthreads();
#pragma unroll
        for (int kk = 0; kk < 16; kk++) {
            float2 a2 = *reinterpret_cast<const float2*>(&As[kk][ty * 2]);
            float4 b4 = *reinterpret_cast<const float4*>(&Bs[kk][tx * 4]);
            acc[0][0] = fmaf(a2.x, b4.x, acc[0][0]);
            acc[0][1] = fmaf(a2.x, b4.y, acc[0][1]);
            acc[0][2] = fmaf(a2.x, b4.z, acc[0][2]);
            acc[0][3] = fmaf(a2.x, b4.w, acc[0][3]);
            acc[1][0] = fmaf(a2.y, b4.x, acc[1][0]);
            acc[1][1] = fmaf(a2.y, b4.y, acc[1][1]);
            acc[1][2] = fmaf(a2.y, b4.z, acc[1][2]);
            acc[1][3] = fmaf(a2.y, b4.w, acc[1][3]);
        }
        __syncthreads();
    }

    int h = h0 + tx;
#pragma unroll
    for (int i = 0; i < 2; i++) {
        int b = bm + ty * 2 + i;
        size_t xrow = (size_t)b * G4;
        float gi = acc[i][0] + xg[xrow + h]          + bih[h]          + bhh[h];
        float gf = acc[i][1] + xg[xrow + Hq + h]     + bih[Hq + h]     + bhh[Hq + h];
        float gg = acc[i][2] + xg[xrow + 2*Hq + h]   + bih[2*Hq + h]   + bhh[2*Hq + h];
        float go = acc[i][3] + xg[xrow + 3*Hq + h]   + bih[3*Hq + h]   + bhh[3*Hq + h];
        int idx = b * Hq + h;
        float cc = d_c[idx];
        float cn = xsigmoid(gf) * cc + xsigmoid(gi) * xtanh(gg);
        float hn = xsigmoid(go) * xtanh(cn);
        d_c[idx] = cn;
        hout[idx] = hn;
        encout[idx] = hn;
    }
}

// ---------------- fused encoder + precompute workers (256 blocks, 2 CTA/SM) ----------------
__global__ __launch_bounds__(256, 2) void k_encfuse(const float* __restrict__ Whh,
                                                    const float* __restrict__ bih,
                                                    const float* __restrict__ bhh,
                                                    const float* __restrict__ Wih_enc,
                                                    const float* __restrict__ Wih_dec,
                                                    const float* __restrict__ Wref) {
    __shared__ float EA[16][34];
    __shared__ float SA[16][132];
    __shared__ float SB[16][68];
    __shared__ unsigned int s_gen0;
    int tid = threadIdx.x, bid = blockIdx.x;

    if (bid < NB_ENC) {
        if (tid == 0) s_gen0 = atomicAdd(&g_gen, 0u);
        __syncthreads();
        unsigned int gen = s_gen0;
        for (int s = 0; s < Sq; s++) {
            if (tid == 0) {
                volatile int* c = d_xgcnt;
                while (c[s] < 32) { }
            }
            __syncthreads();
            const float* hin = d_hbuf + (s & 1) * (Bq * Hq);
            float* hout = d_hbuf + ((s & 1) ^ 1) * (Bq * Hq);
            lstm_phase_enc(bid, tid, hin, hout, Whh, bih, bhh,
                           d_XgEnc + (size_t)s * Bq * G4,
                           d_encout + (size_t)s * Bq * Hq, EA, SB);
            gsync<NB_ENC>(gen, bid);
            if (bid == 0 && tid == 0) atomicExch(&g_enc_done, (unsigned int)(s + 1));
        }
    } else {
        int wd = bid - NB_ENC;
        for (int j = wd; j < 16384; j += NW) {
            int bmT = j >> 4, bnT = j & 15;
            wtile(d_emb, Wih_enc, d_XgEnc, Eq, G4, bmT * 128, bnT * 64, 0, tid, SA, SB);
            __syncthreads();
            if (tid == 0) { __threadfence(); atomicAdd(&d_xgcnt[bmT >> 1], 1); }
        }
        for (int j = wd; j < 16384; j += NW) {
            int bmT = j >> 4, bnT = j & 15;
            wtile(d_emb, Wih_dec, d_Dg, Eq, G4, bmT * 128, bnT * 64, 0, tid, SA, SB);
            __syncthreads();
        }
        {
            size_t total = (size_t)(Sq - 1) * Bq * Sq;
            for (size_t g = (size_t)(wd * 256 + tid); g < total; g += (size_t)NW * 256) {
                int t = (int)(g >> 17);
                unsigned int r = (unsigned int)(g & 131071u);
                d_gum[g] = gumbel_from_bits(tf_bits32(d_keys[2 * t], d_keys[2 * t + 1], r));
            }
        }
        for (int j = wd; j < 4096; j += NW) {
            int bmT = j >> 2, bnT = j & 3;
            unsigned int sneed = (unsigned int)((bmT * 128 + 127) >> 8) + 1u;
            if (tid == 0) {
                volatile unsigned int* p = &g_enc_done;
                while (*p < sneed) { }
            }
            __syncthreads();
            wtile(d_encout, Wref, d_refproj, Hq, Hq, bmT * 128, bnT * 64, 1, tid, SA, SB);
            __syncthreads();
        }
    }
}

// ---------------- persistent decoder: 256 blocks, 2 CTA/SM, 2 phases/step ----------------
__global__ __launch_bounds__(256, 2) void k_decoder(const float* __restrict__ Whh,
                                                    const float* __restrict__ bih,
                                                    const float* __restrict__ bhh,
                                                    const float* __restrict__ vvec) {
    __shared__ float As[16][17];
    __shared__ float Bs[16][68];
    __shared__ __align__(16) float hs[Hq];
    __shared__ __align__(16) float qs[Hq];
    __shared__ __align__(16) float vsm[Hq];
    __shared__ __align__(16) float ls[Sq];
    __shared__ float rv[8];
    __shared__ int   ri[8];
    __shared__ float sv[8];
    __shared__ int   s_ch;
    __shared__ unsigned int s_gen0;

    int tid = threadIdx.x, bid = blockIdx.x;
    if (tid == 0) s_gen0 = atomicAdd(&g_gen, 0u);
    vsm[tid] = vvec[tid];
    __syncthreads();
    unsigned int gen = s_gen0;

    int tbA = bid >> 4, thA = bid & 15;
    int bmA = tbA * 16, h0A = thA * 16;
    int txA = tid & 15, tyA = tid >> 4;
    int w = tid >> 5, lane = tid & 31;
    int b = bid;

    const float4* vs4 = reinterpret_cast<const float4*>(vsm);
    float4 v0 = vs4[lane], v1 = vs4[lane + 32];
    ull vp0 = pk2(v0.x, v0.y), vp1 = pk2(v0.z, v0.w);
    ull vp2 = pk2(v1.x, v1.y), vp3 = pk2(v1.z, v1.w);

    for (int t = 0; t < Sq - 1; t++) {
        const float* hin = d_hbuf + (t & 1) * (Bq * Hq);
        float* hout = d_hbuf + ((t & 1) ^ 1) * (Bq * Hq);

        // ---- Phase A: gates GEMM + LSTM cell (all 256 blocks; 16b x 16h tiles) ----
        {
            float acc[4] = {0.0f, 0.0f, 0.0f, 0.0f};
            for (int k0 = 0; k0 < Hq; k0 += 16) {
                As[tid & 15][tid >> 4] = hin[(bmA + (tid >> 4)) * Hq + k0 + (tid & 15)];
#pragma unroll
                for (int l = 0; l < 4; l++) {
                    int idx = tid + l * 256;
                    int c = idx >> 4, kk = idx & 15;
                    int h = c >> 2, g = c & 3;
                    Bs[kk][c] = Whh[(g * Hq + h0A + h) * Hq + k0 + kk];
                }
                __syncthreads();
#pragma unroll
                for (int kk = 0; kk < 16; kk++) {
                    float a = As[kk][tyA];
                    float4 b4 = *reinterpret_cast<const float4*>(&Bs[kk][txA * 4]);
                    acc[0] = fmaf(a, b4.x, acc[0]);
                    acc[1] = fmaf(a, b4.y, acc[1]);
                    acc[2] = fmaf(a, b4.z, acc[2]);
                    acc[3] = fmaf(a, b4.w, acc[3]);
                }
                __syncthreads();
            }
            int bb = bmA + tyA, h = h0A + txA;
            size_t xrow = ((size_t)d_chosen[bb] * Bq + bb) * G4;
            float gi = acc[0] + d_Dg[xrow + h]          + bih[h]          + bhh[h];
            float gf = acc[1] + d_Dg[xrow + Hq + h]     + bih[Hq + h]     + bhh[Hq + h];
            float gg = acc[2] + d_Dg[xrow + 2*Hq + h]   + bih[2*Hq + h]   + bhh[2*Hq + h];
            float go = acc[3] + d_Dg[xrow + 3*Hq + h]   + bih[3*Hq + h]   + bhh[3*Hq + h];
            int idx = bb * Hq + h;
            float cc = d_c[idx];
            float cn = xsigmoid(gf) * cc + xsigmoid(gi) * xtanh(gg);
            float hn = xsigmoid(go) * xtanh(cn);
            d_c[idx] = cn;
            hout[idx] = hn;
        }
        gsync<NB_DEC>(gen, bid);

        // ---- Phase C: q + attention logits + gumbel argmax + log-softmax ----
        {
            int n = Sq - 1 - t;
            const float* gum = d_gum + ((size_t)t * Bq + b) * Sq;

            hs[tid] = hout[b * Hq + tid];
            ls[tid] = MASKVAL;
            ls[tid + 256] = MASKVAL;
            float g0 = gum[tid], g1 = gum[tid + 256];
            __syncthreads();
            float qv = 0.0f;
#pragma unroll 16
            for (int k = 0; k < Hq; k++)
                qv = fmaf(hs[k], __ldg(&d_WqT[k * Hq + tid]), qv);
            qs[tid] = qv;
            __syncthreads();

            const float4* qs4 = reinterpret_cast<const float4*>(qs);
            float4 q0 = qs4[lane], q1 = qs4[lane + 32];
            const int* lst = d_plist + b * Sq;
            const float* rbase = d_refproj + (size_t)b * Sq * Hq;

            for (int k0 = w * 4; k0 < n; k0 += 32) {
                int4 sxv = *reinterpret_cast<const int4*>(lst + k0);
                int sx[4] = {sxv.x, sxv.y, sxv.z, sxv.w};
                float4 ra[4], rb[4];
#pragma unroll
                for (int j = 0; j < 4; j++) {
                    const float4* p = reinterpret_cast<const float4*>(
                        rbase + (size_t)sx[j] * Hq);
                    ra[j] = p[lane];
                    rb[j] = p[lane + 32];
                }
                float sums[4];
#pragma unroll
                for (int j = 0; j < 4; j++) {
                    ull s2 = 0ULL;
                    ull T;
                    T = xtanh2pk(clamp_pack(q0.x + ra[j].x, q0.y + ra[j].y));
                    s2 = fma2(vp0, T, s2);
                    T = xtanh2pk(clamp_pack(q0.z + ra[j].z, q0.w + ra[j].w));
                    s2 = fma2(vp1, T, s2);
                    T = xtanh2pk(clamp_pack(q1.x + rb[j].x, q1.y + rb[j].y));
                    s2 = fma2(vp2, T, s2);
                    T = xtanh2pk(clamp_pack(q1.z + rb[j].z, q1.w + rb[j].w));
                    s2 = fma2(vp3, T, s2);
                    float lo, hi;
                    upk2(s2, lo, hi);
                    sums[j] = lo + hi;
                }
#pragma unroll
                for (int off = 16; off > 0; off >>= 1) {
                    sums[0] += __shfl_down_sync(0xffffffffu, sums[0], off);
                    sums[1] += __shfl_down_sync(0xffffffffu, sums[1], off);
                    sums[2] += __shfl_down_sync(0xffffffffu, sums[2], off);
                    sums[3] += __shfl_down_sync(0xffffffffu, sums[3], off);
                }
                if (lane == 0) {
#pragma unroll
                    for (int j = 0; j < 4; j++)
                        if (k0 + j < n) ls[sx[j]] = sums[j];
                }
            }
            __syncthreads();

            float l0 = ls[tid], l1 = ls[tid + 256];
            float o0 = (l0 == MASKVAL) ? -1e30f : l0 + g0;
            float o1 = (l1 == MASKVAL) ? -1e30f : l1 + g1;

            // argmax (max value, tie -> min index)
            float bv; int bi;
            if (o0 >= o1) { bv = o0; bi = tid; }
            else { bv = o1; bi = tid + 256; }
#pragma unroll
            for (int off = 16; off > 0; off >>= 1) {
                float ov = __shfl_down_sync(0xffffffffu, bv, off);
                int oi = __shfl_down_sync(0xffffffffu, bi, off);
                if (ov > bv || (ov == bv && oi < bi)) { bv = ov; bi = oi; }
            }
            if (lane == 0) { rv[w] = bv; ri[w] = bi; }
            __syncthreads();
            if (w == 0) {
                float v8 = (lane < 8) ? rv[lane] : -1e38f;
                int i8 = (lane < 8) ? ri[lane] : 0x7fffffff;
#pragma unroll
                for (int off = 4; off > 0; off >>= 1) {
                    float ov = __shfl_down_sync(0xffffffffu, v8, off);
                    int oi = __shfl_down_sync(0xffffffffu, i8, off);
                    if (ov > v8 || (ov == v8 && oi < i8)) { v8 = ov; i8 = oi; }
                }
                if (lane == 0) s_ch = i8;
            }
            __syncthreads();
            int ch = s_ch;

            // max of logits
            float mx = fmaxf(l0, l1);
#pragma unroll
            for (int off = 16; off > 0; off >>= 1)
                mx = fmaxf(mx, __shfl_down_sync(0xffffffffu, mx, off));
            if (lane == 0) rv[w] = mx;
            __syncthreads();
            if (w == 0) {
                float m8 = (lane < 8) ? rv[lane] : -1e38f;
#pragma unroll
                for (int off = 4; off > 0; off >>= 1)
                    m8 = fmaxf(m8, __shfl_down_sync(0xffffffffu, m8, off));
                if (lane == 0) rv[0] = m8;
            }
            __syncthreads();
            float m = rv[0];

            // sum of exp
            float e = expf(l0 - m) + expf(l1 - m);
#pragma unroll
            for (int off = 16; off > 0; off >>= 1)
                e += __shfl_down_sync(0xffffffffu, e, off);
            if (lane == 0) sv[w] = e;
            __syncthreads();
            if (w == 0) {
                float s8 = (lane < 8) ? sv[lane] : 0.0f;
#pragma unroll
                for (int off = 4; off > 0; off >>= 1)
                    s8 += __shfl_down_sync(0xffffffffu, s8, off);
                if (lane == 0) {
                    float lp = (ls[ch] - m) - logf(s8);
                    d_lp[(size_t)t * Bq + b] = lp;
                    d_idx[(size_t)t * Bq + b] = ch;
                    d_chosen[b] = ch;
                    int base = b * Sq;
                    int kk = d_ppos[base + ch];
                    int sl = d_plist[base + n - 1];
                    d_plist[base + kk] = sl;
                    d_ppos[base + sl] = kk;
                    d_plist[base + n - 1] = ch;
                }
            }
        }
        gsync<NB_DEC>(gen, bid);
    }
}

// ---------------- init ----------------
__global__ __launch_bounds__(256) void k_init() {
    int i = blockIdx.x * 256 + threadIdx.x;
    if (i < 2 * Bq * Hq) d_hbuf[i] = 0.0f;
    if (i < Bq * Hq) d_c[i] = 0.0f;
    if (i < Bq * Sq) {
        int bb = i >> 9, s = i & (Sq - 1);
        if (s > 0) {
            d_plist[bb * Sq + (s - 1)] = s;
            d_ppos[bb * Sq + s] = s - 1;
        } else {
            d_plist[bb * Sq + (Sq - 1)] = 0;
            d_ppos[bb * Sq] = -1;
        }
    }
    if (i < Bq) d_chosen[i] = 0;
    if (i < Sq) d_xgcnt[i] = 0;
    if (i < 8 * 32) g_cnt1[i] = 0u;
    if (i == 0) { g_enc_done = 0u; g_cntr = 0u; }
    if (i < (Sq - 1)) {
        unsigned int o0, o1;
        threefry2x32(0u, 1u, 0u, (unsigned int)i, o0, o1);
        d_keys[2 * i] = o0;
        d_keys[2 * i + 1] = o1;
    }
}

__global__ __launch_bounds__(256) void k_trans(const float* __restrict__ Wq) {
    int i = blockIdx.x * 256 + threadIdx.x;
    int k = i >> 8, h = i & 255;
    d_WqT[k * Hq + h] = Wq[h * Hq + k];
}

__global__ __launch_bounds__(256) void k_embed(const float* __restrict__ inputs,
                                               const float* __restrict__ W_embed) {
    int i = blockIdx.x * 256 + threadIdx.x;
    int e = i & (Eq - 1);
    int b = (i >> 8) & (Bq - 1);
    int s = i >> 16;
    const float* inp = inputs + ((size_t)b * Sq + s) * 2;
    d_emb[i] = fmaf(inp[1], W_embed[Eq + e], inp[0] * W_embed[e]);
}

__global__ __launch_bounds__(256) void k_final(float* __restrict__ out) {
    int i = blockIdx.x * 256 + threadIdx.x;
    const int NLP = Bq * (Sq - 1);
    if (i < NLP) {
        int b = i / (Sq - 1), t = i % (Sq - 1);
        out[i] = d_lp[(size_t)t * Bq + b];
    } else if (i < NLP + Bq * Sq) {
        int j = i - NLP;
        int b = j >> 9, s = j & (Sq - 1);
        out[i] = (s == 0) ? 0.0f : (float)d_idx[(size_t)(s - 1) * Bq + b];
    }
}

// ---------------- host ----------------
extern "C" void kernel_launch(void* const* d_in, const int* in_sizes, int n_in,
                              void* d_out, int out_size) {
    const float* inputs   = (const float*)d_in[0];
    const float* W_embed  = (const float*)d_in[1];
    const float* enc_Wih  = (const float*)d_in[2];
    const float* enc_Whh  = (const float*)d_in[3];
    const float* enc_bih  = (const float*)d_in[4];
    const float* enc_bhh  = (const float*)d_in[5];
    const float* dec_Wih  = (const float*)d_in[6];
    const float* dec_Whh  = (const float*)d_in[7];
    const float* dec_bih  = (const float*)d_in[8];
    const float* dec_bhh  = (const float*)d_in[9];
    const float* Wq       = (const float*)d_in[10];
    const float* Wref     = (const float*)d_in[11];
    const float* v        = (const float*)d_in[12];

    k_init<<<512, 256>>>();
    k_trans<<<256, 256>>>(Wq);
    k_embed<<<(Sq * Bq * Eq) / 256, 256>>>(inputs, W_embed);

    // fused: encoder (blocks 0-127) + precompute workers (blocks 128-255)
    k_encfuse<<<NB_ENC + NW, 256>>>(enc_Whh, enc_bih, enc_bhh,
                                    enc_Wih, dec_Wih, Wref);

    k_decoder<<<NB_DEC, 256>>>(dec_Whh, dec_bih, dec_bhh, v);

    k_final<<<(Bq * (Sq - 1) + Bq * Sq + 255) / 256, 256>>>((float*)d_out);
}

// round 14
// speedup vs baseline: 1.3750x; 1.0330x over previous
#include <cuda_runtime.h>
#include <cstdint>

#define Bq 256
#define Sq 512
#define Eq 256
#define Hq 256
#define G4 1024
#define NB_ENC 128
#define NW 128
#define NB_DEC 256
#define MASKVAL -100000.0f
#define TINYF 1.17549435e-38f
#define CLV 7.90531110763549805f

typedef unsigned long long ull;

// ---------------- device globals (static scratch) ----------------
__device__ float d_emb[(size_t)Sq * Bq * Eq];        // [s][b][e]
__device__ float d_XgEnc[(size_t)Sq * Bq * G4];      // [s][b][j]
__device__ float d_Dg[(size_t)Sq * Bq * G4];         // [s][b][j]
__device__ float d_encout[(size_t)Sq * Bq * Hq];     // [s][b][h]
__device__ float d_refproj[(size_t)Bq * Sq * Hq];    // [b][s][h]
__device__ float d_gum[(size_t)(Sq - 1) * Bq * Sq];  // [t][b][s]
__device__ float d_WqT[Hq * Hq];                     // [k][h]
__device__ int d_rmaxI[Bq * Sq];                     // [b][s] max_h |refproj| (float bits)
__device__ float d_hbuf[2 * Bq * Hq];
__device__ float d_c[Bq * Hq];
__device__ int d_plist[Bq * Sq];
__device__ int d_ppos[Bq * Sq];
__device__ int d_chosen[Bq];
__device__ unsigned int d_keys[(Sq - 1) * 2];
__device__ float d_lp[(Sq - 1) * Bq];
__device__ int d_idx[(Sq - 1) * Bq];
__device__ int d_xgcnt[Sq];
__device__ unsigned int g_enc_done = 0;
__device__ unsigned int g_cnt = 0;
__device__ unsigned int g_gen = 0;

// ---------------- f32x2 packed helpers ----------------
__device__ __forceinline__ ull pk2(float lo, float hi) {
    ull r;
    asm("mov.b64 %0, {%1, %2};" : "=l"(r) : "f"(lo), "f"(hi));
    return r;
}
__device__ __forceinline__ void upk2(ull v, float& lo, float& hi) {
    asm("mov.b64 {%0, %1}, %2;" : "=f"(lo), "=f"(hi) : "l"(v));
}
__device__ __forceinline__ ull fma2(ull a, ull b, ull c) {
    ull d;
    asm("fma.rn.f32x2 %0, %1, %2, %3;" : "=l"(d) : "l"(a), "l"(b), "l"(c));
    return d;
}
__device__ __forceinline__ ull mul2(ull a, ull b) {
    ull d;
    asm("mul.rn.f32x2 %0, %1, %2;" : "=l"(d) : "l"(a), "l"(b));
    return d;
}
__device__ __forceinline__ ull add2(ull a, ull b) {
    ull d;
    asm("add.rn.f32x2 %0, %1, %2;" : "=l"(d) : "l"(a), "l"(b));
    return d;
}
__device__ __forceinline__ ull pk1(float c) { return pk2(c, c); }

// ---------------- math helpers ----------------
__device__ __forceinline__ float xtanh(float x) {
    float ax = fabsf(x);
    float xc = fminf(fmaxf(x, -CLV), CLV);
    float x2 = xc * xc;
    float p = -2.76076847742355e-16f;
    p = fmaf(p, x2, 2.00018790482477e-13f);
    p = fmaf(p, x2, -8.60467152213735e-11f);
    p = fmaf(p, x2, 5.12229709037114e-08f);
    p = fmaf(p, x2, 1.48572235717979e-05f);
    p = fmaf(p, x2, 6.37261928875436e-04f);
    p = fmaf(p, x2, 4.89352455891786e-03f);
    float q = 1.19825839466702e-06f;
    q = fmaf(q, x2, 1.18534705686654e-04f);
    q = fmaf(q, x2, 2.26843463243900e-03f);
    q = fmaf(q, x2, 4.89352518554385e-03f);
    float t = (xc * p) / q;
    return (ax < 0.0004f) ? x : t;
}

// packed tanh core: poly exact, rcp.approx + 1 NR (~1 ulp). X must be in-range or pre-clamped.
__device__ __forceinline__ ull xtanh2pk(ull X) {
    ull x2 = mul2(X, X);
    ull p = pk1(-2.76076847742355e-16f);
    p = fma2(p, x2, pk1(2.00018790482477e-13f));
    p = fma2(p, x2, pk1(-8.60467152213735e-11f));
    p = fma2(p, x2, pk1(5.12229709037114e-08f));
    p = fma2(p, x2, pk1(1.48572235717979e-05f));
    p = fma2(p, x2, pk1(6.37261928875436e-04f));
    p = fma2(p, x2, pk1(4.89352455891786e-03f));
    ull q = pk1(1.19825839466702e-06f);
    q = fma2(q, x2, pk1(1.18534705686654e-04f));
    q = fma2(q, x2, pk1(2.26843463243900e-03f));
    q = fma2(q, x2, pk1(4.89352518554385e-03f));
    ull num = mul2(X, p);
    float qa, qb;
    upk2(q, qa, qb);
    float ra, rb;
    asm("rcp.approx.f32 %0, %1;" : "=f"(ra) : "f"(qa));
    asm("rcp.approx.f32 %0, %1;" : "=f"(rb) : "f"(qb));
    ull rr = pk2(ra, rb);
    ull nq = q ^ 0x8000000080000000ULL;
    ull e = fma2(nq, rr, pk1(1.0f));
    rr = fma2(e, rr, rr);
    return mul2(num, rr);
}

__device__ __forceinline__ ull clamp_pack(float a, float b) {
    float ca = fminf(fmaxf(a, -CLV), CLV);
    float cb = fminf(fmaxf(b, -CLV), CLV);
    return pk2(ca, cb);
}

__device__ __forceinline__ float xsigmoid(float x) {
    return 1.0f / (1.0f + expf(-x));
}

__device__ __forceinline__ unsigned int rotl32(unsigned int v, int r) {
    return (v << r) | (v >> (32 - r));
}

__device__ __forceinline__ void threefry2x32(unsigned int k0, unsigned int k1,
                                             unsigned int x0, unsigned int x1,
                                             unsigned int& o0, unsigned int& o1) {
    unsigned int ks2 = k0 ^ k1 ^ 0x1BD11BDAu;
    x0 += k0; x1 += k1;
#define TF_RND(r) { x0 += x1; x1 = rotl32(x1, r); x1 ^= x0; }
    TF_RND(13) TF_RND(15) TF_RND(26) TF_RND(6)
    x0 += k1; x1 += ks2 + 1u;
    TF_RND(17) TF_RND(29) TF_RND(16) TF_RND(24)
    x0 += ks2; x1 += k0 + 2u;
    TF_RND(13) TF_RND(15) TF_RND(26) TF_RND(6)
    x0 += k0; x1 += k1 + 3u;
    TF_RND(17) TF_RND(29) TF_RND(16) TF_RND(24)
    x0 += k1; x1 += ks2 + 4u;
    TF_RND(13) TF_RND(15) TF_RND(26) TF_RND(6)
    x0 += ks2; x1 += k0 + 5u;
#undef TF_RND
    o0 = x0; o1 = x1;
}

__device__ __forceinline__ unsigned int tf_bits32(unsigned int k0, unsigned int k1,
                                                  unsigned int idx) {
    unsigned int o0, o1;
    threefry2x32(k0, k1, 0u, idx, o0, o1);
    return o0 ^ o1;
}

__device__ __forceinline__ float gumbel_from_bits(unsigned int bits) {
    float f = __uint_as_float((bits >> 9) | 0x3f800000u) - 1.0f;
    float u = f + TINYF;
    u = fmaxf(TINYF, u);
    return -logf(-logf(u));
}

// ---------------- grid-wide barrier (simple, R9-proven) ----------------
template <int NBLK>
__device__ __forceinline__ void gsync(unsigned int& gen) {
    __syncthreads();
    if (threadIdx.x == 0) {
        __threadfence();
        unsigned int t = atomicAdd(&g_cnt, 1u);
        if (t == NBLK - 1) {
            atomicExch(&g_cnt, 0u);
            __threadfence();
            atomicExch(&g_gen, gen + 1);
        } else {
            volatile unsigned int* p = &g_gen;
            while ((int)(*p - (gen + 1)) < 0) { }
            __threadfence();
        }
    }
    gen++;
    __syncthreads();
}

// ---------------- worker GEMM tile: C[128 x 64] = A[M][K] @ W[N][K]^T ----------------
__device__ void wtile(const float* __restrict__ A, const float* __restrict__ W,
                      float* __restrict__ C, int K, int N, int bm, int bn,
                      int transOut, int tid, float (*As)[132], float (*Bs)[68],
                      int* __restrict__ rmaxI) {
    int tx = tid & 15, ty = tid >> 4;
    float acc[8][4];
#pragma unroll
    for (int i = 0; i < 8; i++)
#pragma unroll
        for (int j = 0; j < 4; j++) acc[i][j] = 0.0f;

    for (int k0 = 0; k0 < K; k0 += 16) {
#pragma unroll
        for (int l = 0; l < 2; l++) {
            int slot = tid + l * 256;
            int r = slot >> 2, c4 = slot & 3;
            float4 va = *reinterpret_cast<const float4*>(&A[(size_t)(bm + r) * K + k0 + c4 * 4]);
            As[c4 * 4 + 0][r] = va.x;
            As[c4 * 4 + 1][r] = va.y;
            As[c4 * 4 + 2][r] = va.z;
            As[c4 * 4 + 3][r] = va.w;
        }
        {
            int r = tid >> 2, c4 = tid & 3;
            float4 vb = *reinterpret_cast<const float4*>(&W[(size_t)(bn + r) * K + k0 + c4 * 4]);
            Bs[c4 * 4 + 0][r] = vb.x;
            Bs[c4 * 4 + 1][r] = vb.y;
            Bs[c4 * 4 + 2][r] = vb.z;
            Bs[c4 * 4 + 3][r] = vb.w;
        }
        __syncthreads();
#pragma unroll
        for (int kk = 0; kk < 16; kk++) {
            float4 a0 = *reinterpret_cast<const float4*>(&As[kk][ty * 8]);
            float4 a1 = *reinterpret_cast<const float4*>(&As[kk][ty * 8 + 4]);
            float4 b0 = *reinterpret_cast<const float4*>(&Bs[kk][tx * 4]);
            float a[8] = {a0.x, a0.y, a0.z, a0.w, a1.x, a1.y, a1.z, a1.w};
            float b[4] = {b0.x, b0.y, b0.z, b0.w};
#pragma unroll
            for (int i = 0; i < 8; i++)
#pragma unroll
                for (int j = 0; j < 4; j++)
                    acc[i][j] = fmaf(a[i], b[j], acc[i][j]);
        }
        __syncthreads();
    }
#pragma unroll
    for (int i = 0; i < 8; i++) {
        int m = bm + ty * 8 + i;
        size_t row = transOut ? ((size_t)(m & (Bq - 1)) * Sq + (m >> 8)) : (size_t)m;
        *reinterpret_cast<float4*>(&C[row * N + bn + tx * 4]) =
            make_float4(acc[i][0], acc[i][1], acc[i][2], acc[i][3]);
        if (rmaxI) {
            float vm = fmaxf(fmaxf(fabsf(acc[i][0]), fabsf(acc[i][1])),
                             fmaxf(fabsf(acc[i][2]), fabsf(acc[i][3])));
            atomicMax(&rmaxI[row], __float_as_int(vm));
        }
    }
}

// ---------------- encoder lstm phase (128 blocks, 32b x 16h tiles) ----------------
__device__ __forceinline__ void lstm_phase_enc(
    int bid, int tid,
    const float* __restrict__ hin, float* __restrict__ hout,
    const float* __restrict__ Whh, const float* __restrict__ bih,
    const float* __restrict__ bhh,
    const float* __restrict__ xg,
    float* __restrict__ encout,
    float (*As)[34], float (*Bs)[68])
{
    int tb = bid >> 4, th = bid & 15;
    int bm = tb * 32, h0 = th * 16;
    int tx = tid & 15, ty = tid >> 4;
    float acc[2][4];
#pragma unroll
    for (int i = 0; i < 2; i++)
#pragma unroll
        for (int g = 0; g < 4; g++) acc[i][g] = 0.0f;

    for (int k0 = 0; k0 < Hq; k0 += 16) {
#pragma unroll
        for (int l = 0; l < 2; l++) {
            int idx = tid + l * 256;
            int m = idx >> 4, kk = idx & 15;
            As[kk][m] = hin[(bm + m) * Hq + k0 + kk];
        }
#pragma unroll
        for (int l = 0; l < 4; l++) {
            int idx = tid + l * 256;
            int c = idx >> 4, kk = idx & 15;
            int h = c >> 2, g = c & 3;
            Bs[kk][c] = Whh[(g * Hq + h0 + h) * Hq + k0 + kk];
        }
        __syncthreads();
#pragma unroll
        for (int kk = 0; kk < 16; kk++) {
            float2 a2 = *reinterpret_cast<const float2*>(&As[kk][ty * 2]);
            float4 b4 = *reinterpret_cast<const float4*>(&Bs[kk][tx * 4]);
            acc[0][0] = fmaf(a2.x, b4.x, acc[0][0]);
            acc[0][1] = fmaf(a2.x, b4.y, acc[0][1]);
            acc[0][2] = fmaf(a2.x, b4.z, acc[0][2]);
            acc[0][3] = fmaf(a2.x, b4.w, acc[0][3]);
            acc[1][0] = fmaf(a2.y, b4.x, acc[1][0]);
            acc[1][1] = fmaf(a2.y, b4.y, acc[1][1]);
            acc[1][2] = fmaf(a2.y, b4.z, acc[1][2]);
            acc[1][3] = fmaf(a2.y, b4.w, acc[1][3]);
        }
        __syncthreads();
    }

    int h = h0 + tx;
#pragma unroll
    for (int i = 0; i < 2; i++) {
        int b = bm + ty * 2 + i;
        size_t xrow = (size_t)b * G4;
        float gi = acc[i][0] + xg[xrow + h]          + bih[h]          + bhh[h];
        float gf = acc[i][1] + xg[xrow + Hq + h]     + bih[Hq + h]     + bhh[Hq + h];
        float gg = acc[i][2] + xg[xrow + 2*Hq + h]   + bih[2*Hq + h]   + bhh[2*Hq + h];
        float go = acc[i][3] + xg[xrow + 3*Hq + h]   + bih[3*Hq + h]   + bhh[3*Hq + h];
        int idx = b * Hq + h;
        float cc = d_c[idx];
        float cn = xsigmoid(gf) * cc + xsigmoid(gi) * xtanh(gg);
        float hn = xsigmoid(go) * xtanh(cn);
        d_c[idx] = cn;
        hout[idx] = hn;
        encout[idx] = hn;
    }
}

// ---------------- fused encoder + precompute workers (256 blocks, 2 CTA/SM) ----------------
__global__ __launch_bounds__(256, 2) void k_encfuse(const float* __restrict__ Whh,
                                                    const float* __restrict__ bih,
                                                    const float* __restrict__ bhh,
                                                    const float* __restrict__ Wih_enc,
                                                    const float* __restrict__ Wih_dec,
                                                    const float* __restrict__ Wref) {
    __shared__ float EA[16][34];
    __shared__ float SA[16][132];
    __shared__ float SB[16][68];
    __shared__ unsigned int s_gen0;
    int tid = threadIdx.x, bid = blockIdx.x;

    if (bid < NB_ENC) {
        if (tid == 0) s_gen0 = atomicAdd(&g_gen, 0u);
        __syncthreads();
        unsigned int gen = s_gen0;
        for (int s = 0; s < Sq; s++) {
            if (tid == 0) {
                volatile int* c = d_xgcnt;
                while (c[s] < 32) { }
            }
            __syncthreads();
            const float* hin = d_hbuf + (s & 1) * (Bq * Hq);
            float* hout = d_hbuf + ((s & 1) ^ 1) * (Bq * Hq);
            lstm_phase_enc(bid, tid, hin, hout, Whh, bih, bhh,
                           d_XgEnc + (size_t)s * Bq * G4,
                           d_encout + (size_t)s * Bq * Hq, EA, SB);
            gsync<NB_ENC>(gen);
            if (bid == 0 && tid == 0) atomicExch(&g_enc_done, (unsigned int)(s + 1));
        }
    } else {
        int wd = bid - NB_ENC;
        for (int j = wd; j < 16384; j += NW) {
            int bmT = j >> 4, bnT = j & 15;
            wtile(d_emb, Wih_enc, d_XgEnc, Eq, G4, bmT * 128, bnT * 64, 0, tid, SA, SB, nullptr);
            __syncthreads();
            if (tid == 0) { __threadfence(); atomicAdd(&d_xgcnt[bmT >> 1], 1); }
        }
        for (int j = wd; j < 16384; j += NW) {
            int bmT = j >> 4, bnT = j & 15;
            wtile(d_emb, Wih_dec, d_Dg, Eq, G4, bmT * 128, bnT * 64, 0, tid, SA, SB, nullptr);
            __syncthreads();
        }
        {
            size_t total = (size_t)(Sq - 1) * Bq * Sq;
            for (size_t g = (size_t)(wd * 256 + tid); g < total; g += (size_t)NW * 256) {
                int t = (int)(g >> 17);
                unsigned int r = (unsigned int)(g & 131071u);
                d_gum[g] = gumbel_from_bits(tf_bits32(d_keys[2 * t], d_keys[2 * t + 1], r));
            }
        }
        for (int j = wd; j < 4096; j += NW) {
            int bmT = j >> 2, bnT = j & 3;
            unsigned int sneed = (unsigned int)((bmT * 128 + 127) >> 8) + 1u;
            if (tid == 0) {
                volatile unsigned int* p = &g_enc_done;
                while (*p < sneed) { }
            }
            __syncthreads();
            wtile(d_encout, Wref, d_refproj, Hq, Hq, bmT * 128, bnT * 64, 1, tid, SA, SB, d_rmaxI);
            __syncthreads();
        }
    }
}

// ---------------- persistent decoder: 256 blocks, 2 CTA/SM, 2 phases/step ----------------
__global__ __launch_bounds__(256, 2) void k_decoder(const float* __restrict__ Whh,
                                                    const float* __restrict__ bih,
                                                    const float* __restrict__ bhh,
                                                    const float* __restrict__ vvec) {
    __shared__ float As[16][17];
    __shared__ float Bs[16][68];
    __shared__ __align__(16) float hs[Hq];
    __shared__ __align__(16) float qs[Hq];
    __shared__ __align__(16) float vsm[Hq];
    __shared__ __align__(16) float ls[Sq];
    __shared__ float rv[8];
    __shared__ int   ri[8];
    __shared__ float sv[8];
    __shared__ int   s_ch;
    __shared__ unsigned int s_gen0;

    int tid = threadIdx.x, bid = blockIdx.x;
    if (tid == 0) s_gen0 = atomicAdd(&g_gen, 0u);
    vsm[tid] = vvec[tid];
    __syncthreads();
    unsigned int gen = s_gen0;

    int tbA = bid >> 4, thA = bid & 15;
    int bmA = tbA * 16, h0A = thA * 16;
    int txA = tid & 15, tyA = tid >> 4;
    int w = tid >> 5, lane = tid & 31;
    int b = bid;

    const float4* vs4 = reinterpret_cast<const float4*>(vsm);
    float4 v0 = vs4[lane], v1 = vs4[lane + 32];
    ull vp0 = pk2(v0.x, v0.y), vp1 = pk2(v0.z, v0.w);
    ull vp2 = pk2(v1.x, v1.y), vp3 = pk2(v1.z, v1.w);

    for (int t = 0; t < Sq - 1; t++) {
        const float* hin = d_hbuf + (t & 1) * (Bq * Hq);
        float* hout = d_hbuf + ((t & 1) ^ 1) * (Bq * Hq);

        // ---- Phase A: gates GEMM + LSTM cell (all 256 blocks; 16b x 16h tiles) ----
        {
            float acc[4] = {0.0f, 0.0f, 0.0f, 0.0f};
            for (int k0 = 0; k0 < Hq; k0 += 16) {
                As[tid & 15][tid >> 4] = hin[(bmA + (tid >> 4)) * Hq + k0 + (tid & 15)];
#pragma unroll
                for (int l = 0; l < 4; l++) {
                    int idx = tid + l * 256;
                    int c = idx >> 4, kk = idx & 15;
                    int h = c >> 2, g = c & 3;
                    Bs[kk][c] = Whh[(g * Hq + h0A + h) * Hq + k0 + kk];
                }
                __syncthreads();
#pragma unroll
                for (int kk = 0; kk < 16; kk++) {
                    float a = As[kk][tyA];
                    float4 b4 = *reinterpret_cast<const float4*>(&Bs[kk][txA * 4]);
                    acc[0] = fmaf(a, b4.x, acc[0]);
                    acc[1] = fmaf(a, b4.y, acc[1]);
                    acc[2] = fmaf(a, b4.z, acc[2]);
                    acc[3] = fmaf(a, b4.w, acc[3]);
                }
                __syncthreads();
            }
            int bb = bmA + tyA, h = h0A + txA;
            size_t xrow = ((size_t)d_chosen[bb] * Bq + bb) * G4;
            float gi = acc[0] + d_Dg[xrow + h]          + bih[h]          + bhh[h];
            float gf = acc[1] + d_Dg[xrow + Hq + h]     + bih[Hq + h]     + bhh[Hq + h];
            float gg = acc[2] + d_Dg[xrow + 2*Hq + h]   + bih[2*Hq + h]   + bhh[2*Hq + h];
            float go = acc[3] + d_Dg[xrow + 3*Hq + h]   + bih[3*Hq + h]   + bhh[3*Hq + h];
            int idx = bb * Hq + h;
            float cc = d_c[idx];
            float cn = xsigmoid(gf) * cc + xsigmoid(gi) * xtanh(gg);
            float hn = xsigmoid(go) * xtanh(cn);
            d_c[idx] = cn;
            hout[idx] = hn;
        }
        gsync<NB_DEC>(gen);

        // ---- Phase C: q + attention logits + gumbel argmax + log-softmax ----
        {
            int n = Sq - 1 - t;
            const float* gum = d_gum + ((size_t)t * Bq + b) * Sq;

            hs[tid] = hout[b * Hq + tid];
            ls[tid] = MASKVAL;
            ls[tid + 256] = MASKVAL;
            float g0 = gum[tid], g1 = gum[tid + 256];
            __syncthreads();
            // q GEMV with 4 interleaved chains (latency ~4x lower; ~1e-7 class change)
            float s0 = 0.0f, s1 = 0.0f, s2 = 0.0f, s3 = 0.0f;
#pragma unroll 8
            for (int k = 0; k < Hq; k += 4) {
                s0 = fmaf(hs[k],     __ldg(&d_WqT[k * Hq + tid]),       s0);
                s1 = fmaf(hs[k + 1], __ldg(&d_WqT[(k + 1) * Hq + tid]), s1);
                s2 = fmaf(hs[k + 2], __ldg(&d_WqT[(k + 2) * Hq + tid]), s2);
                s3 = fmaf(hs[k + 3], __ldg(&d_WqT[(k + 3) * Hq + tid]), s3);
            }
            float qv = (s0 + s1) + (s2 + s3);
            qs[tid] = qv;
            // per-block max|q| for the clamp-skip bound
            float aq = fabsf(qv);
#pragma unroll
            for (int off = 16; off > 0; off >>= 1)
                aq = fmaxf(aq, __shfl_xor_sync(0xffffffffu, aq, off));
            if (lane == 0) sv[w] = aq;
            __syncthreads();
            float mq = fmaxf(fmaxf(fmaxf(sv[0], sv[1]), fmaxf(sv[2], sv[3])),
                             fmaxf(fmaxf(sv[4], sv[5]), fmaxf(sv[6], sv[7])));

            const float4* qs4 = reinterpret_cast<const float4*>(qs);
            float4 tq0 = qs4[lane], tq1 = qs4[lane + 32];
            ull qp0 = pk2(tq0.x, tq0.y), qp1 = pk2(tq0.z, tq0.w);
            ull qp2 = pk2(tq1.x, tq1.y), qp3 = pk2(tq1.z, tq1.w);
            const int* lst = d_plist + b * Sq;
            const float* rbase = d_refproj + (size_t)b * Sq * Hq;

            for (int k0 = w * 4; k0 < n; k0 += 32) {
                int4 sxv = *reinterpret_cast<const int4*>(lst + k0);
                int sx[4] = {sxv.x, sxv.y, sxv.z, sxv.w};
                float rm = fmaxf(
                    fmaxf(__int_as_float(d_rmaxI[b * Sq + sx[0]]),
                          __int_as_float(d_rmaxI[b * Sq + sx[1]])),
                    fmaxf(__int_as_float(d_rmaxI[b * Sq + sx[2]]),
                          __int_as_float(d_rmaxI[b * Sq + sx[3]])));
                bool safe = (mq + rm <= CLV);
                ulonglong2 ua[4], ub[4];
#pragma unroll
                for (int j = 0; j < 4; j++) {
                    const ulonglong2* p = reinterpret_cast<const ulonglong2*>(
                        rbase + (size_t)sx[j] * Hq);
                    ua[j] = p[lane];
                    ub[j] = p[lane + 32];
                }
                float sums[4];
                if (safe) {
                    // clamp-free path: clamp is identity when |q+r| <= CLV (bit-identical)
#pragma unroll
                    for (int j = 0; j < 4; j++) {
                        ull s2p = 0ULL;
                        s2p = fma2(vp0, xtanh2pk(add2(qp0, ua[j].x)), s2p);
                        s2p = fma2(vp1, xtanh2pk(add2(qp1, ua[j].y)), s2p);
                        s2p = fma2(vp2, xtanh2pk(add2(qp2, ub[j].x)), s2p);
                        s2p = fma2(vp3, xtanh2pk(add2(qp3, ub[j].y)), s2p);
                        float lo, hi;
                        upk2(s2p, lo, hi);
                        sums[j] = lo + hi;
                    }
                } else {
                    // exact clamped path (same bits as before)
#pragma unroll
                    for (int j = 0; j < 4; j++) {
                        ull s2p = 0ULL;
                        float x0, x1;
                        upk2(add2(qp0, ua[j].x), x0, x1);
                        s2p = fma2(vp0, xtanh2pk(clamp_pack(x0, x1)), s2p);
                        upk2(add2(qp1, ua[j].y), x0, x1);
                        s2p = fma2(vp1, xtanh2pk(clamp_pack(x0, x1)), s2p);
                        upk2(add2(qp2, ub[j].x), x0, x1);
                        s2p = fma2(vp2, xtanh2pk(clamp_pack(x0, x1)), s2p);
                        upk2(add2(qp3, ub[j].y), x0, x1);
                        s2p = fma2(vp3, xtanh2pk(clamp_pack(x0, x1)), s2p);
                        float lo, hi;
                        upk2(s2p, lo, hi);
                        sums[j] = lo + hi;
                    }
                }
#pragma unroll
                for (int off = 16; off > 0; off >>= 1) {
                    sums[0] += __shfl_down_sync(0xffffffffu, sums[0], off);
                    sums[1] += __shfl_down_sync(0xffffffffu, sums[1], off);
                    sums[2] += __shfl_down_sync(0xffffffffu, sums[2], off);
                    sums[3] += __shfl_down_sync(0xffffffffu, sums[3], off);
                }
                if (lane == 0) {
#pragma unroll
                    for (int j = 0; j < 4; j++)
                        if (k0 + j < n) ls[sx[j]] = sums[j];
                }
            }
            __syncthreads();

            float l0 = ls[tid], l1 = ls[tid + 256];
            float o0 = (l0 == MASKVAL) ? -1e30f : l0 + g0;
            float o1 = (l1 == MASKVAL) ? -1e30f : l1 + g1;

            // argmax (max value, tie -> min index)
            float bv; int bi;
            if (o0 >= o1) { bv = o0; bi = tid; }
            else { bv = o1; bi = tid + 256; }
#pragma unroll
            for (int off = 16; off > 0; off >>= 1) {
                float ov = __shfl_down_sync(0xffffffffu, bv, off);
                int oi = __shfl_down_sync(0xffffffffu, bi, off);
                if (ov > bv || (ov == bv && oi < bi)) { bv = ov; bi = oi; }
            }
            if (lane == 0) { rv[w] = bv; ri[w] = bi; }
            __syncthreads();
            if (w == 0) {
                float v8 = (lane < 8) ? rv[lane] : -1e38f;
                int i8 = (lane < 8) ? ri[lane] : 0x7fffffff;
#pragma unroll
                for (int off = 4; off > 0; off >>= 1) {
                    float ov = __shfl_down_sync(0xffffffffu, v8, off);
                    int oi = __shfl_down_sync(0xffffffffu, i8, off);
                    if (ov > v8 || (ov == v8 && oi < i8)) { v8 = ov; i8 = oi; }
                }
                if (lane == 0) s_ch = i8;
            }
            __syncthreads();
            int ch = s_ch;

            // max of logits
            float mx = fmaxf(l0, l1);
#pragma unroll
            for (int off = 16; off > 0; off >>= 1)
                mx = fmaxf(mx, __shfl_down_sync(0xffffffffu, mx, off));
            if (lane == 0) rv[w] = mx;
            __syncthreads();
            if (w == 0) {
                float m8 = (lane < 8) ? rv[lane] : -1e38f;
#pragma unroll
                for (int off = 4; off > 0; off >>= 1)
                    m8 = fmaxf(m8, __shfl_down_sync(0xffffffffu, m8, off));
                if (lane == 0) rv[0] = m8;
            }
            __syncthreads();
            float m = rv[0];

            // sum of exp
            float e = expf(l0 - m) + expf(l1 - m);
#pragma unroll
            for (int off = 16; off > 0; off >>= 1)
                e += __shfl_down_sync(0xffffffffu, e, off);
            if (lane == 0) sv[w] = e;
            __syncthreads();
            if (w == 0) {
                float s8 = (lane < 8) ? sv[lane] : 0.0f;
#pragma unroll
                for (int off = 4; off > 0; off >>= 1)
                    s8 += __shfl_down_sync(0xffffffffu, s8, off);
                if (lane == 0) {
                    float lp = (ls[ch] - m) - logf(s8);
                    d_lp[(size_t)t * Bq + b] = lp;
                    d_idx[(size_t)t * Bq + b] = ch;
                    d_chosen[b] = ch;
                    int base = b * Sq;
                    int kk = d_ppos[base + ch];
                    int sl = d_plist[base + n - 1];
                    d_plist[base + kk] = sl;
                    d_ppos[base + sl] = kk;
                    d_plist[base + n - 1] = ch;
                }
            }
        }
        gsync<NB_DEC>(gen);
    }
}

// ---------------- init ----------------
__global__ __launch_bounds__(256) void k_init() {
    int i = blockIdx.x * 256 + threadIdx.x;
    if (i < 2 * Bq * Hq) d_hbuf[i] = 0.0f;
    if (i < Bq * Hq) d_c[i] = 0.0f;
    if (i < Bq * Sq) {
        int bb = i >> 9, s = i & (Sq - 1);
        d_rmaxI[i] = 0;
        if (s > 0) {
            d_plist[bb * Sq + (s - 1)] = s;
            d_ppos[bb * Sq + s] = s - 1;
        } else {
            d_plist[bb * Sq + (Sq - 1)] = 0;
            d_ppos[bb * Sq] = -1;
        }
    }
    if (i < Bq) d_chosen[i] = 0;
    if (i < Sq) d_xgcnt[i] = 0;
    if (i == 0) { g_enc_done = 0u; g_cnt = 0u; }
    if (i < (Sq - 1)) {
        unsigned int o0, o1;
        threefry2x32(0u, 1u, 0u, (unsigned int)i, o0, o1);
        d_keys[2 * i] = o0;
        d_keys[2 * i + 1] = o1;
    }
}

__global__ __launch_bounds__(256) void k_trans(const float* __restrict__ Wq) {
    int i = blockIdx.x * 256 + threadIdx.x;
    int k = i >> 8, h = i & 255;
    d_WqT[k * Hq + h] = Wq[h * Hq + k];
}

__global__ __launch_bounds__(256) void k_embed(const float* __restrict__ inputs,
                                               const float* __restrict__ W_embed) {
    int i = blockIdx.x * 256 + threadIdx.x;
    int e = i & (Eq - 1);
    int b = (i >> 8) & (Bq - 1);
    int s = i >> 16;
    const float* inp = inputs + ((size_t)b * Sq + s) * 2;
    d_emb[i] = fmaf(inp[1], W_embed[Eq + e], inp[0] * W_embed[e]);
}

__global__ __launch_bounds__(256) void k_final(float* __restrict__ out) {
    int i = blockIdx.x * 256 + threadIdx.x;
    const int NLP = Bq * (Sq - 1);
    if (i < NLP) {
        int b = i / (Sq - 1), t = i % (Sq - 1);
        out[i] = d_lp[(size_t)t * Bq + b];
    } else if (i < NLP + Bq * Sq) {
        int j = i - NLP;
        int b = j >> 9, s = j & (Sq - 1);
        out[i] = (s == 0) ? 0.0f : (float)d_idx[(size_t)(s - 1) * Bq + b];
    }
}

// ---------------- host ----------------
extern "C" void kernel_launch(void* const* d_in, const int* in_sizes, int n_in,
                              void* d_out, int out_size) {
    const float* inputs   = (const float*)d_in[0];
    const float* W_embed  = (const float*)d_in[1];
    const float* enc_Wih  = (const float*)d_in[2];
    const float* enc_Whh  = (const float*)d_in[3];
    const float* enc_bih  = (const float*)d_in[4];
    const float* enc_bhh  = (const float*)d_in[5];
    const float* dec_Wih  = (const float*)d_in[6];
    const float* dec_Whh  = (const float*)d_in[7];
    const float* dec_bih  = (const float*)d_in[8];
    const float* dec_bhh  = (const float*)d_in[9];
    const float* Wq       = (const float*)d_in[10];
    const float* Wref     = (const float*)d_in[11];
    const float* v        = (const float*)d_in[12];

    k_init<<<512, 256>>>();
    k_trans<<<256, 256>>>(Wq);
    k_embed<<<(Sq * Bq * Eq) / 256, 256>>>(inputs, W_embed);

    // fused: encoder (blocks 0-127) + precompute workers (blocks 128-255)
    k_encfuse<<<NB_ENC + NW, 256>>>(enc_Whh, enc_bih, enc_bhh,
                                    enc_Wih, dec_Wih, Wref);

    k_decoder<<<NB_DEC, 256>>>(dec_Whh, dec_bih, dec_bhh, v);

    k_final<<<(Bq * (Sq - 1) + Bq * Sq + 255) / 256, 256>>>((float*)d_out);
}

// round 15
// speedup vs baseline: 1.4505x; 1.0549x over previous
#include <cuda_runtime.h>
#include <cstdint>

#define Bq 256
#define Sq 512
#define Eq 256
#define Hq 256
#define G4 1024
#define NB_ENC 128
#define NW 128
#define NB_DEC 256
#define MASKVAL -100000.0f
#define TINYF 1.17549435e-38f
#define CLV 7.90531110763549805f

typedef unsigned long long ull;

// ---------------- device globals (static scratch) ----------------
__device__ float d_emb[(size_t)Sq * Bq * Eq];        // [s][b][e]
__device__ float d_XgEnc[(size_t)Sq * Bq * G4];      // [s][b][j]
__device__ float d_Dg[(size_t)Sq * Bq * G4];         // [s][b][j]
__device__ float d_encout[(size_t)Sq * Bq * Hq];     // [s][b][h]
__device__ float d_refproj[(size_t)Bq * Sq * Hq];    // [b][s][h]
__device__ float d_gum[(size_t)(Sq - 1) * Bq * Sq];  // [t][b][s]
__device__ float d_WqT[Hq * Hq];                     // [k][h]
__device__ int d_rmaxI[Bq * Sq];                     // [b][s] max_h |refproj| (float bits)
__device__ float d_hbuf[2 * Bq * Hq];
__device__ float d_c[Bq * Hq];
__device__ int d_plist[Bq * Sq];
__device__ int d_ppos[Bq * Sq];
__device__ int d_chosen[Bq];
__device__ unsigned int d_keys[(Sq - 1) * 2];
__device__ float d_lp[(Sq - 1) * Bq];
__device__ int d_idx[(Sq - 1) * Bq];
__device__ int d_xgcnt[Sq];
__device__ unsigned int g_enc_done = 0;
__device__ unsigned int g_cnt = 0;
__device__ unsigned int g_gen = 0;

// ---------------- f32x2 packed helpers ----------------
__device__ __forceinline__ ull pk2(float lo, float hi) {
    ull r;
    asm("mov.b64 %0, {%1, %2};" : "=l"(r) : "f"(lo), "f"(hi));
    return r;
}
__device__ __forceinline__ void upk2(ull v, float& lo, float& hi) {
    asm("mov.b64 {%0, %1}, %2;" : "=f"(lo), "=f"(hi) : "l"(v));
}
__device__ __forceinline__ ull fma2(ull a, ull b, ull c) {
    ull d;
    asm("fma.rn.f32x2 %0, %1, %2, %3;" : "=l"(d) : "l"(a), "l"(b), "l"(c));
    return d;
}
__device__ __forceinline__ ull mul2(ull a, ull b) {
    ull d;
    asm("mul.rn.f32x2 %0, %1, %2;" : "=l"(d) : "l"(a), "l"(b));
    return d;
}
__device__ __forceinline__ ull add2(ull a, ull b) {
    ull d;
    asm("add.rn.f32x2 %0, %1, %2;" : "=l"(d) : "l"(a), "l"(b));
    return d;
}
__device__ __forceinline__ ull pk1(float c) { return pk2(c, c); }

// ---------------- math helpers ----------------
__device__ __forceinline__ float xtanh(float x) {
    float ax = fabsf(x);
    float xc = fminf(fmaxf(x, -CLV), CLV);
    float x2 = xc * xc;
    float p = -2.76076847742355e-16f;
    p = fmaf(p, x2, 2.00018790482477e-13f);
    p = fmaf(p, x2, -8.60467152213735e-11f);
    p = fmaf(p, x2, 5.12229709037114e-08f);
    p = fmaf(p, x2, 1.48572235717979e-05f);
    p = fmaf(p, x2, 6.37261928875436e-04f);
    p = fmaf(p, x2, 4.89352455891786e-03f);
    float q = 1.19825839466702e-06f;
    q = fmaf(q, x2, 1.18534705686654e-04f);
    q = fmaf(q, x2, 2.26843463243900e-03f);
    q = fmaf(q, x2, 4.89352518554385e-03f);
    float t = (xc * p) / q;
    return (ax < 0.0004f) ? x : t;
}

// packed tanh core: poly exact, rcp.approx + 1 NR (~1 ulp). X must be in-range or pre-clamped.
__device__ __forceinline__ ull xtanh2pk(ull X) {
    ull x2 = mul2(X, X);
    ull p = pk1(-2.76076847742355e-16f);
    p = fma2(p, x2, pk1(2.00018790482477e-13f));
    p = fma2(p, x2, pk1(-8.60467152213735e-11f));
    p = fma2(p, x2, pk1(5.12229709037114e-08f));
    p = fma2(p, x2, pk1(1.48572235717979e-05f));
    p = fma2(p, x2, pk1(6.37261928875436e-04f));
    p = fma2(p, x2, pk1(4.89352455891786e-03f));
    ull q = pk1(1.19825839466702e-06f);
    q = fma2(q, x2, pk1(1.18534705686654e-04f));
    q = fma2(q, x2, pk1(2.26843463243900e-03f));
    q = fma2(q, x2, pk1(4.89352518554385e-03f));
    ull num = mul2(X, p);
    float qa, qb;
    upk2(q, qa, qb);
    float ra, rb;
    asm("rcp.approx.f32 %0, %1;" : "=f"(ra) : "f"(qa));
    asm("rcp.approx.f32 %0, %1;" : "=f"(rb) : "f"(qb));
    ull rr = pk2(ra, rb);
    ull nq = q ^ 0x8000000080000000ULL;
    ull e = fma2(nq, rr, pk1(1.0f));
    rr = fma2(e, rr, rr);
    return mul2(num, rr);
}

__device__ __forceinline__ ull clamp_pack(float a, float b) {
    float ca = fminf(fmaxf(a, -CLV), CLV);
    float cb = fminf(fmaxf(b, -CLV), CLV);
    return pk2(ca, cb);
}

__device__ __forceinline__ float xsigmoid(float x) {
    return 1.0f / (1.0f + expf(-x));
}

__device__ __forceinline__ unsigned int rotl32(unsigned int v, int r) {
    return (v << r) | (v >> (32 - r));
}

__device__ __forceinline__ void threefry2x32(unsigned int k0, unsigned int k1,
                                             unsigned int x0, unsigned int x1,
                                             unsigned int& o0, unsigned int& o1) {
    unsigned int ks2 = k0 ^ k1 ^ 0x1BD11BDAu;
    x0 += k0; x1 += k1;
#define TF_RND(r) { x0 += x1; x1 = rotl32(x1, r); x1 ^= x0; }
    TF_RND(13) TF_RND(15) TF_RND(26) TF_RND(6)
    x0 += k1; x1 += ks2 + 1u;
    TF_RND(17) TF_RND(29) TF_RND(16) TF_RND(24)
    x0 += ks2; x1 += k0 + 2u;
    TF_RND(13) TF_RND(15) TF_RND(26) TF_RND(6)
    x0 += k0; x1 += k1 + 3u;
    TF_RND(17) TF_RND(29) TF_RND(16) TF_RND(24)
    x0 += k1; x1 += ks2 + 4u;
    TF_RND(13) TF_RND(15) TF_RND(26) TF_RND(6)
    x0 += ks2; x1 += k0 + 5u;
#undef TF_RND
    o0 = x0; o1 = x1;
}

__device__ __forceinline__ unsigned int tf_bits32(unsigned int k0, unsigned int k1,
                                                  unsigned int idx) {
    unsigned int o0, o1;
    threefry2x32(k0, k1, 0u, idx, o0, o1);
    return o0 ^ o1;
}

__device__ __forceinline__ float gumbel_from_bits(unsigned int bits) {
    float f = __uint_as_float((bits >> 9) | 0x3f800000u) - 1.0f;
    float u = f + TINYF;
    u = fmaxf(TINYF, u);
    return -logf(-logf(u));
}

// ---------------- grid-wide barrier (simple, R9-proven) ----------------
template <int NBLK>
__device__ __forceinline__ void gsync(unsigned int& gen) {
    __syncthreads();
    if (threadIdx.x == 0) {
        __threadfence();
        unsigned int t = atomicAdd(&g_cnt, 1u);
        if (t == NBLK - 1) {
            atomicExch(&g_cnt, 0u);
            __threadfence();
            atomicExch(&g_gen, gen + 1);
        } else {
            volatile unsigned int* p = &g_gen;
            while ((int)(*p - (gen + 1)) < 0) { }
            __threadfence();
        }
    }
    gen++;
    __syncthreads();
}

// ---------------- worker GEMM tile: C[128 x 64] = A[M][K] @ W[N][K]^T ----------------
__device__ void wtile(const float* __restrict__ A, const float* __restrict__ W,
                      float* __restrict__ C, int K, int N, int bm, int bn,
                      int transOut, int tid, float (*As)[132], float (*Bs)[68],
                      int* __restrict__ rmaxI) {
    int tx = tid & 15, ty = tid >> 4;
    float acc[8][4];
#pragma unroll
    for (int i = 0; i < 8; i++)
#pragma unroll
        for (int j = 0; j < 4; j++) acc[i][j] = 0.0f;

    for (int k0 = 0; k0 < K; k0 += 16) {
#pragma unroll
        for (int l = 0; l < 2; l++) {
            int slot = tid + l * 256;
            int r = slot >> 2, c4 = slot & 3;
            float4 va = *reinterpret_cast<const float4*>(&A[(size_t)(bm + r) * K + k0 + c4 * 4]);
            As[c4 * 4 + 0][r] = va.x;
            As[c4 * 4 + 1][r] = va.y;
            As[c4 * 4 + 2][r] = va.z;
            As[c4 * 4 + 3][r] = va.w;
        }
        {
            int r = tid >> 2, c4 = tid & 3;
            float4 vb = *reinterpret_cast<const float4*>(&W[(size_t)(bn + r) * K + k0 + c4 * 4]);
            Bs[c4 * 4 + 0][r] = vb.x;
            Bs[c4 * 4 + 1][r] = vb.y;
            Bs[c4 * 4 + 2][r] = vb.z;
            Bs[c4 * 4 + 3][r] = vb.w;
        }
        __syncthreads();
#pragma unroll
        for (int kk = 0; kk < 16; kk++) {
            float4 a0 = *reinterpret_cast<const float4*>(&As[kk][ty * 8]);
            float4 a1 = *reinterpret_cast<const float4*>(&As[kk][ty * 8 + 4]);
            float4 b0 = *reinterpret_cast<const float4*>(&Bs[kk][tx * 4]);
            float a[8] = {a0.x, a0.y, a0.z, a0.w, a1.x, a1.y, a1.z, a1.w};
            float b[4] = {b0.x, b0.y, b0.z, b0.w};
#pragma unroll
            for (int i = 0; i < 8; i++)
#pragma unroll
                for (int j = 0; j < 4; j++)
                    acc[i][j] = fmaf(a[i], b[j], acc[i][j]);
        }
        __syncthreads();
    }
#pragma unroll
    for (int i = 0; i < 8; i++) {
        int m = bm + ty * 8 + i;
        size_t row = transOut ? ((size_t)(m & (Bq - 1)) * Sq + (m >> 8)) : (size_t)m;
        *reinterpret_cast<float4*>(&C[row * N + bn + tx * 4]) =
            make_float4(acc[i][0], acc[i][1], acc[i][2], acc[i][3]);
        if (rmaxI) {
            float vm = fmaxf(fmaxf(fabsf(acc[i][0]), fabsf(acc[i][1])),
                             fmaxf(fabsf(acc[i][2]), fabsf(acc[i][3])));
            atomicMax(&rmaxI[row], __float_as_int(vm));
        }
    }
}

// ---------------- encoder lstm phase (128 blocks, 32b x 16h tiles) ----------------
__device__ __forceinline__ void lstm_phase_enc(
    int bid, int tid,
    const float* __restrict__ hin, float* __restrict__ hout,
    const float* __restrict__ Whh, const float* __restrict__ bih,
    const float* __restrict__ bhh,
    const float* __restrict__ xg,
    float* __restrict__ encout,
    float (*As)[34], float (*Bs)[68])
{
    int tb = bid >> 4, th = bid & 15;
    int bm = tb * 32, h0 = th * 16;
    int tx = tid & 15, ty = tid >> 4;
    float acc[2][4];
#pragma unroll
    for (int i = 0; i < 2; i++)
#pragma unroll
        for (int g = 0; g < 4; g++) acc[i][g] = 0.0f;

    for (int k0 = 0; k0 < Hq; k0 += 16) {
#pragma unroll
        for (int l = 0; l < 2; l++) {
            int idx = tid + l * 256;
            int m = idx >> 4, kk = idx & 15;
            As[kk][m] = hin[(bm + m) * Hq + k0 + kk];
        }
#pragma unroll
        for (int l = 0; l < 4; l++) {
            int idx = tid + l * 256;
            int c = idx >> 4, kk = idx & 15;
            int h = c >> 2, g = c & 3;
            Bs[kk][c] = Whh[(g * Hq + h0 + h) * Hq + k0 + kk];
        }
        __syncthreads();
#pragma unroll
        for (int kk = 0; kk < 16; kk++) {
            float2 a2 = *reinterpret_cast<const float2*>(&As[kk][ty * 2]);
            float4 b4 = *reinterpret_cast<const float4*>(&Bs[kk][tx * 4]);
            acc[0][0] = fmaf(a2.x, b4.x, acc[0][0]);
            acc[0][1] = fmaf(a2.x, b4.y, acc[0][1]);
            acc[0][2] = fmaf(a2.x, b4.z, acc[0][2]);
            acc[0][3] = fmaf(a2.x, b4.w, acc[0][3]);
            acc[1][0] = fmaf(a2.y, b4.x, acc[1][0]);
            acc[1][1] = fmaf(a2.y, b4.y, acc[1][1]);
            acc[1][2] = fmaf(a2.y, b4.z, acc[1][2]);
            acc[1][3] = fmaf(a2.y, b4.w, acc[1][3]);
        }
        __syncthreads();
    }

    int h = h0 + tx;
#pragma unroll
    for (int i = 0; i < 2; i++) {
        int b = bm + ty * 2 + i;
        size_t xrow = (size_t)b * G4;
        float gi = acc[i][0] + xg[xrow + h]          + bih[h]          + bhh[h];
        float gf = acc[i][1] + xg[xrow + Hq + h]     + bih[Hq + h]     + bhh[Hq + h];
        float gg = acc[i][2] + xg[xrow + 2*Hq + h]   + bih[2*Hq + h]   + bhh[2*Hq + h];
        float go = acc[i][3] + xg[xrow + 3*Hq + h]   + bih[3*Hq + h]   + bhh[3*Hq + h];
        int idx = b * Hq + h;
        float cc = d_c[idx];
        float cn = xsigmoid(gf) * cc + xsigmoid(gi) * xtanh(gg);
        float hn = xsigmoid(go) * xtanh(cn);
        d_c[idx] = cn;
        hout[idx] = hn;
        encout[idx] = hn;
    }
}

// ---------------- fused encoder + precompute workers (256 blocks, 2 CTA/SM) ----------------
__global__ __launch_bounds__(256, 2) void k_encfuse(const float* __restrict__ Whh,
                                                    const float* __restrict__ bih,
                                                    const float* __restrict__ bhh,
                                                    const float* __restrict__ Wih_enc,
                                                    const float* __restrict__ Wih_dec,
                                                    const float* __restrict__ Wref) {
    __shared__ float EA[16][34];
    __shared__ float SA[16][132];
    __shared__ float SB[16][68];
    __shared__ unsigned int s_gen0;
    int tid = threadIdx.x, bid = blockIdx.x;

    if (bid < NB_ENC) {
        if (tid == 0) s_gen0 = atomicAdd(&g_gen, 0u);
        __syncthreads();
        unsigned int gen = s_gen0;
        for (int s = 0; s < Sq; s++) {
            if (tid == 0) {
                volatile int* c = d_xgcnt;
                while (c[s] < 32) { }
            }
            __syncthreads();
            const float* hin = d_hbuf + (s & 1) * (Bq * Hq);
            float* hout = d_hbuf + ((s & 1) ^ 1) * (Bq * Hq);
            lstm_phase_enc(bid, tid, hin, hout, Whh, bih, bhh,
                           d_XgEnc + (size_t)s * Bq * G4,
                           d_encout + (size_t)s * Bq * Hq, EA, SB);
            gsync<NB_ENC>(gen);
            if (bid == 0 && tid == 0) atomicExch(&g_enc_done, (unsigned int)(s + 1));
        }
    } else {
        int wd = bid - NB_ENC;
        for (int j = wd; j < 16384; j += NW) {
            int bmT = j >> 4, bnT = j & 15;
            wtile(d_emb, Wih_enc, d_XgEnc, Eq, G4, bmT * 128, bnT * 64, 0, tid, SA, SB, nullptr);
            __syncthreads();
            if (tid == 0) { __threadfence(); atomicAdd(&d_xgcnt[bmT >> 1], 1); }
        }
        for (int j = wd; j < 16384; j += NW) {
            int bmT = j >> 4, bnT = j & 15;
            wtile(d_emb, Wih_dec, d_Dg, Eq, G4, bmT * 128, bnT * 64, 0, tid, SA, SB, nullptr);
            __syncthreads();
        }
        {
            size_t total = (size_t)(Sq - 1) * Bq * Sq;
            for (size_t g = (size_t)(wd * 256 + tid); g < total; g += (size_t)NW * 256) {
                int t = (int)(g >> 17);
                unsigned int r = (unsigned int)(g & 131071u);
                d_gum[g] = gumbel_from_bits(tf_bits32(d_keys[2 * t], d_keys[2 * t + 1], r));
            }
        }
        for (int j = wd; j < 4096; j += NW) {
            int bmT = j >> 2, bnT = j & 3;
            unsigned int sneed = (unsigned int)((bmT * 128 + 127) >> 8) + 1u;
            if (tid == 0) {
                volatile unsigned int* p = &g_enc_done;
                while (*p < sneed) { }
            }
            __syncthreads();
            wtile(d_encout, Wref, d_refproj, Hq, Hq, bmT * 128, bnT * 64, 1, tid, SA, SB, d_rmaxI);
            __syncthreads();
        }
    }
}

// ---------------- persistent decoder: 256 blocks, 2 CTA/SM, 2 phases/step ----------------
__global__ __launch_bounds__(256, 2) void k_decoder(const float* __restrict__ Whh,
                                                    const float* __restrict__ bih,
                                                    const float* __restrict__ bhh,
                                                    const float* __restrict__ vvec) {
    __shared__ float As[16][17];
    __shared__ float Bs[16][68];
    __shared__ __align__(16) float hs[Hq];
    __shared__ __align__(16) float qs[Hq];
    __shared__ __align__(16) float vsm[Hq];
    __shared__ __align__(16) float ls[Sq];
    __shared__ float sbih[64];
    __shared__ float sbhh[64];
    __shared__ float rv[8];
    __shared__ int   ri[8];
    __shared__ float sv[8];
    __shared__ int   s_ch;
    __shared__ unsigned int s_gen0;

    int tid = threadIdx.x, bid = blockIdx.x;
    if (tid == 0) s_gen0 = atomicAdd(&g_gen, 0u);
    vsm[tid] = vvec[tid];

    int tbA = bid >> 4, thA = bid & 15;
    int bmA = tbA * 16, h0A = thA * 16;
    int txA = tid & 15, tyA = tid >> 4;
    int w = tid >> 5, lane = tid & 31;
    int b = bid;

    // stage biases for this block's h-range once (same values, same add order later)
    if (tid < 64) {
        int g = tid >> 4, hh = tid & 15;
        sbih[tid] = bih[g * Hq + h0A + hh];
        sbhh[tid] = bhh[g * Hq + h0A + hh];
    }

    // per-b rmax over all s (for the hoisted clamp-skip bound)
    float rmb = 0.0f;
    for (int s = tid; s < Sq; s += 256)
        rmb = fmaxf(rmb, __int_as_float(d_rmaxI[b * Sq + s]));
#pragma unroll
    for (int off = 16; off > 0; off >>= 1)
        rmb = fmaxf(rmb, __shfl_xor_sync(0xffffffffu, rmb, off));
    if (lane == 0) sv[w] = rmb;
    __syncthreads();
    float rmaxb = fmaxf(fmaxf(fmaxf(sv[0], sv[1]), fmaxf(sv[2], sv[3])),
                        fmaxf(fmaxf(sv[4], sv[5]), fmaxf(sv[6], sv[7])));
    unsigned int gen = s_gen0;
    __syncthreads();

    const float4* vs4 = reinterpret_cast<const float4*>(vsm);
    float4 v0 = vs4[lane], v1 = vs4[lane + 32];
    ull vp0 = pk2(v0.x, v0.y), vp1 = pk2(v0.z, v0.w);
    ull vp2 = pk2(v1.x, v1.y), vp3 = pk2(v1.z, v1.w);

    for (int t = 0; t < Sq - 1; t++) {
        const float* hin = d_hbuf + (t & 1) * (Bq * Hq);
        float* hout = d_hbuf + ((t & 1) ^ 1) * (Bq * Hq);

        // ---- Phase A: gates GEMM + LSTM cell (all 256 blocks; 16b x 16h tiles) ----
        {
            // front-load gather + cell-state loads so their latency hides under the GEMM
            int bb = bmA + tyA, h = h0A + txA;
            int idx = bb * Hq + h;
            size_t xrow = ((size_t)d_chosen[bb] * Bq + bb) * G4;
            float xg0 = d_Dg[xrow + h];
            float xg1 = d_Dg[xrow + Hq + h];
            float xg2 = d_Dg[xrow + 2 * Hq + h];
            float xg3 = d_Dg[xrow + 3 * Hq + h];
            float cc = d_c[idx];

            float acc[4] = {0.0f, 0.0f, 0.0f, 0.0f};
            for (int k0 = 0; k0 < Hq; k0 += 16) {
                As[tid & 15][tid >> 4] = hin[(bmA + (tid >> 4)) * Hq + k0 + (tid & 15)];
#pragma unroll
                for (int l = 0; l < 4; l++) {
                    int idx2 = tid + l * 256;
                    int c = idx2 >> 4, kk = idx2 & 15;
                    int hh = c >> 2, g = c & 3;
                    Bs[kk][c] = Whh[(g * Hq + h0A + hh) * Hq + k0 + kk];
                }
                __syncthreads();
#pragma unroll
                for (int kk = 0; kk < 16; kk++) {
                    float a = As[kk][tyA];
                    float4 b4 = *reinterpret_cast<const float4*>(&Bs[kk][txA * 4]);
                    acc[0] = fmaf(a, b4.x, acc[0]);
                    acc[1] = fmaf(a, b4.y, acc[1]);
                    acc[2] = fmaf(a, b4.z, acc[2]);
                    acc[3] = fmaf(a, b4.w, acc[3]);
                }
                __syncthreads();
            }
            float gi = acc[0] + xg0 + sbih[txA]      + sbhh[txA];
            float gf = acc[1] + xg1 + sbih[16 + txA] + sbhh[16 + txA];
            float gg = acc[2] + xg2 + sbih[32 + txA] + sbhh[32 + txA];
            float go = acc[3] + xg3 + sbih[48 + txA] + sbhh[48 + txA];
            float cn = xsigmoid(gf) * cc + xsigmoid(gi) * xtanh(gg);
            float hn = xsigmoid(go) * xtanh(cn);
            d_c[idx] = cn;
            hout[idx] = hn;
        }
        gsync<NB_DEC>(gen);

        // ---- Phase C: q + attention logits + gumbel argmax + log-softmax ----
        {
            int n = Sq - 1 - t;
            const float* gum = d_gum + ((size_t)t * Bq + b) * Sq;

            hs[tid] = hout[b * Hq + tid];
            ls[tid] = MASKVAL;
            ls[tid + 256] = MASKVAL;
            float g0 = gum[tid], g1 = gum[tid + 256];
            __syncthreads();
            // q GEMV with 4 interleaved chains
            float s0 = 0.0f, s1 = 0.0f, s2 = 0.0f, s3 = 0.0f;
#pragma unroll 8
            for (int k = 0; k < Hq; k += 4) {
                s0 = fmaf(hs[k],     __ldg(&d_WqT[k * Hq + tid]),       s0);
                s1 = fmaf(hs[k + 1], __ldg(&d_WqT[(k + 1) * Hq + tid]), s1);
                s2 = fmaf(hs[k + 2], __ldg(&d_WqT[(k + 2) * Hq + tid]), s2);
                s3 = fmaf(hs[k + 3], __ldg(&d_WqT[(k + 3) * Hq + tid]), s3);
            }
            float qv = (s0 + s1) + (s2 + s3);
            qs[tid] = qv;
            // per-block max|q|
            float aq = fabsf(qv);
#pragma unroll
            for (int off = 16; off > 0; off >>= 1)
                aq = fmaxf(aq, __shfl_xor_sync(0xffffffffu, aq, off));
            if (lane == 0) sv[w] = aq;
            __syncthreads();
            float mq = fmaxf(fmaxf(fmaxf(sv[0], sv[1]), fmaxf(sv[2], sv[3])),
                             fmaxf(fmaxf(sv[4], sv[5]), fmaxf(sv[6], sv[7])));
            bool safe = (mq + rmaxb <= CLV);

            const float4* qs4 = reinterpret_cast<const float4*>(qs);
            float4 tq0 = qs4[lane], tq1 = qs4[lane + 32];
            ull qp0 = pk2(tq0.x, tq0.y), qp1 = pk2(tq0.z, tq0.w);
            ull qp2 = pk2(tq1.x, tq1.y), qp3 = pk2(tq1.z, tq1.w);
            const int* lst = d_plist + b * Sq;
            const float* rbase = d_refproj + (size_t)b * Sq * Hq;

            if (safe) {
                // clamp-free path (bit-identical: clamp is identity when |q+r| <= CLV)
                int k0 = w * 4;
                int4 sxv;
                if (k0 < n) sxv = *reinterpret_cast<const int4*>(lst + k0);
                for (; k0 < n; k0 += 32) {
                    // prefetch next iteration's candidate indices
                    int4 sxn;
                    if (k0 + 32 < n) sxn = *reinterpret_cast<const int4*>(lst + k0 + 32);
                    int sx[4] = {sxv.x, sxv.y, sxv.z, sxv.w};
                    ulonglong2 ua[4], ub[4];
#pragma unroll
                    for (int j = 0; j < 4; j++) {
                        const ulonglong2* p = reinterpret_cast<const ulonglong2*>(
                            rbase + (size_t)sx[j] * Hq);
                        ua[j] = p[lane];
                        ub[j] = p[lane + 32];
                    }
                    float sums[4];
#pragma unroll
                    for (int j = 0; j < 4; j++) {
                        ull s2p = 0ULL;
                        s2p = fma2(vp0, xtanh2pk(add2(qp0, ua[j].x)), s2p);
                        s2p = fma2(vp1, xtanh2pk(add2(qp1, ua[j].y)), s2p);
                        s2p = fma2(vp2, xtanh2pk(add2(qp2, ub[j].x)), s2p);
                        s2p = fma2(vp3, xtanh2pk(add2(qp3, ub[j].y)), s2p);
                        float lo, hi;
                        upk2(s2p, lo, hi);
                        sums[j] = lo + hi;
                    }
#pragma unroll
                    for (int off = 16; off > 0; off >>= 1) {
                        sums[0] += __shfl_down_sync(0xffffffffu, sums[0], off);
                        sums[1] += __shfl_down_sync(0xffffffffu, sums[1], off);
                        sums[2] += __shfl_down_sync(0xffffffffu, sums[2], off);
                        sums[3] += __shfl_down_sync(0xffffffffu, sums[3], off);
                    }
                    if (lane == 0) {
#pragma unroll
                        for (int j = 0; j < 4; j++)
                            if (k0 + j < n) ls[sx[j]] = sums[j];
                    }
                    sxv = sxn;
                }
            } else {
                // exact clamped path
                for (int k0 = w * 4; k0 < n; k0 += 32) {
                    int4 sxv = *reinterpret_cast<const int4*>(lst + k0);
                    int sx[4] = {sxv.x, sxv.y, sxv.z, sxv.w};
                    ulonglong2 ua[4], ub[4];
#pragma unroll
                    for (int j = 0; j < 4; j++) {
                        const ulonglong2* p = reinterpret_cast<const ulonglong2*>(
                            rbase + (size_t)sx[j] * Hq);
                        ua[j] = p[lane];
                        ub[j] = p[lane + 32];
                    }
                    float sums[4];
#pragma unroll
                    for (int j = 0; j < 4; j++) {
                        ull s2p = 0ULL;
                        float x0, x1;
                        upk2(add2(qp0, ua[j].x), x0, x1);
                        s2p = fma2(vp0, xtanh2pk(clamp_pack(x0, x1)), s2p);
                        upk2(add2(qp1, ua[j].y), x0, x1);
                        s2p = fma2(vp1, xtanh2pk(clamp_pack(x0, x1)), s2p);
                        upk2(add2(qp2, ub[j].x), x0, x1);
                        s2p = fma2(vp2, xtanh2pk(clamp_pack(x0, x1)), s2p);
                        upk2(add2(qp3, ub[j].y), x0, x1);
                        s2p = fma2(vp3, xtanh2pk(clamp_pack(x0, x1)), s2p);
                        float lo, hi;
                        upk2(s2p, lo, hi);
                        sums[j] = lo + hi;
                    }
#pragma unroll
                    for (int off = 16; off > 0; off >>= 1) {
                        sums[0] += __shfl_down_sync(0xffffffffu, sums[0], off);
                        sums[1] += __shfl_down_sync(0xffffffffu, sums[1], off);
                        sums[2] += __shfl_down_sync(0xffffffffu, sums[2], off);
                        sums[3] += __shfl_down_sync(0xffffffffu, sums[3], off);
                    }
                    if (lane == 0) {
#pragma unroll
                        for (int j = 0; j < 4; j++)
                            if (k0 + j < n) ls[sx[j]] = sums[j];
                    }
                }
            }
            __syncthreads();

            float l0 = ls[tid], l1 = ls[tid + 256];
            float o0 = (l0 == MASKVAL) ? -1e30f : l0 + g0;
            float o1 = (l1 == MASKVAL) ? -1e30f : l1 + g1;

            // argmax (max value, tie -> min index)
            float bv; int bi;
            if (o0 >= o1) { bv = o0; bi = tid; }
            else { bv = o1; bi = tid + 256; }
#pragma unroll
            for (int off = 16; off > 0; off >>= 1) {
                float ov = __shfl_down_sync(0xffffffffu, bv, off);
                int oi = __shfl_down_sync(0xffffffffu, bi, off);
                if (ov > bv || (ov == bv && oi < bi)) { bv = ov; bi = oi; }
            }
            if (lane == 0) { rv[w] = bv; ri[w] = bi; }
            __syncthreads();
            if (w == 0) {
                float v8 = (lane < 8) ? rv[lane] : -1e38f;
                int i8 = (lane < 8) ? ri[lane] : 0x7fffffff;
#pragma unroll
                for (int off = 4; off > 0; off >>= 1) {
                    float ov = __shfl_down_sync(0xffffffffu, v8, off);
                    int oi = __shfl_down_sync(0xffffffffu, i8, off);
                    if (ov > v8 || (ov == v8 && oi < i8)) { v8 = ov; i8 = oi; }
                }
                if (lane == 0) s_ch = i8;
            }
            __syncthreads();
            int ch = s_ch;

            // max of logits
            float mx = fmaxf(l0, l1);
#pragma unroll
            for (int off = 16; off > 0; off >>= 1)
                mx = fmaxf(mx, __shfl_down_sync(0xffffffffu, mx, off));
            if (lane == 0) rv[w] = mx;
            __syncthreads();
            if (w == 0) {
                float m8 = (lane < 8) ? rv[lane] : -1e38f;
#pragma unroll
                for (int off = 4; off > 0; off >>= 1)
                    m8 = fmaxf(m8, __shfl_down_sync(0xffffffffu, m8, off));
                if (lane == 0) rv[0] = m8;
            }
            __syncthreads();
            float m = rv[0];

            // sum of exp
            float e = expf(l0 - m) + expf(l1 - m);
#pragma unroll
            for (int off = 16; off > 0; off >>= 1)
                e += __shfl_down_sync(0xffffffffu, e, off);
            if (lane == 0) sv[w] = e;
            __syncthreads();
            if (w == 0) {
                float s8 = (lane < 8) ? sv[lane] : 0.0f;
#pragma unroll
                for (int off = 4; off > 0; off >>= 1)
                    s8 += __shfl_down_sync(0xffffffffu, s8, off);
                if (lane == 0) {
                    float lp = (ls[ch] - m) - logf(s8);
                    d_lp[(size_t)t * Bq + b] = lp;
                    d_idx[(size_t)t * Bq + b] = ch;
                    d_chosen[b] = ch;
                    int base = b * Sq;
                    int kk = d_ppos[base + ch];
                    int sl = d_plist[base + n - 1];
                    d_plist[base + kk] = sl;
                    d_ppos[base + sl] = kk;
                    d_plist[base + n - 1] = ch;
                }
            }
        }
        gsync<NB_DEC>(gen);
    }
}

// ---------------- init ----------------
__global__ __launch_bounds__(256) void k_init() {
    int i = blockIdx.x * 256 + threadIdx.x;
    if (i < 2 * Bq * Hq) d_hbuf[i] = 0.0f;
    if (i < Bq * Hq) d_c[i] = 0.0f;
    if (i < Bq * Sq) {
        int bb = i >> 9, s = i & (Sq - 1);
        d_rmaxI[i] = 0;
        if (s > 0) {
            d_plist[bb * Sq + (s - 1)] = s;
            d_ppos[bb * Sq + s] = s - 1;
        } else {
            d_plist[bb * Sq + (Sq - 1)] = 0;
            d_ppos[bb * Sq] = -1;
        }
    }
    if (i < Bq) d_chosen[i] = 0;
    if (i < Sq) d_xgcnt[i] = 0;
    if (i == 0) { g_enc_done = 0u; g_cnt = 0u; }
    if (i < (Sq - 1)) {
        unsigned int o0, o1;
        threefry2x32(0u, 1u, 0u, (unsigned int)i, o0, o1);
        d_keys[2 * i] = o0;
        d_keys[2 * i + 1] = o1;
    }
}

__global__ __launch_bounds__(256) void k_trans(const float* __restrict__ Wq) {
    int i = blockIdx.x * 256 + threadIdx.x;
    int k = i >> 8, h = i & 255;
    d_WqT[k * Hq + h] = Wq[h * Hq + k];
}

__global__ __launch_bounds__(256) void k_embed(const float* __restrict__ inputs,
                                               const float* __restrict__ W_embed) {
    int i = blockIdx.x * 256 + threadIdx.x;
    int e = i & (Eq - 1);
    int b = (i >> 8) & (Bq - 1);
    int s = i >> 16;
    const float* inp = inputs + ((size_t)b * Sq + s) * 2;
    d_emb[i] = fmaf(inp[1], W_embed[Eq + e], inp[0] * W_embed[e]);
}

__global__ __launch_bounds__(256) void k_final(float* __restrict__ out) {
    int i = blockIdx.x * 256 + threadIdx.x;
    const int NLP = Bq * (Sq - 1);
    if (i < NLP) {
        int b = i / (Sq - 1), t = i % (Sq - 1);
        out[i] = d_lp[(size_t)t * Bq + b];
    } else if (i < NLP + Bq * Sq) {
        int j = i - NLP;
        int b = j >> 9, s = j & (Sq - 1);
        out[i] = (s == 0) ? 0.0f : (float)d_idx[(size_t)(s - 1) * Bq + b];
    }
}

// ---------------- host ----------------
extern "C" void kernel_launch(void* const* d_in, const int* in_sizes, int n_in,
                              void* d_out, int out_size) {
    const float* inputs   = (const float*)d_in[0];
    const float* W_embed  = (const float*)d_in[1];
    const float* enc_Wih  = (const float*)d_in[2];
    const float* enc_Whh  = (const float*)d_in[3];
    const float* enc_bih  = (const float*)d_in[4];
    const float* enc_bhh  = (const float*)d_in[5];
    const float* dec_Wih  = (const float*)d_in[6];
    const float* dec_Whh  = (const float*)d_in[7];
    const float* dec_bih  = (const float*)d_in[8];
    const float* dec_bhh  = (const float*)d_in[9];
    const float* Wq       = (const float*)d_in[10];
    const float* Wref     = (const float*)d_in[11];
    const float* v        = (const float*)d_in[12];

    k_init<<<512, 256>>>();
    k_trans<<<256, 256>>>(Wq);
    k_embed<<<(Sq * Bq * Eq) / 256, 256>>>(inputs, W_embed);

    // fused: encoder (blocks 0-127) + precompute workers (blocks 128-255)
    k_encfuse<<<NB_ENC + NW, 256>>>(enc_Whh, enc_bih, enc_bhh,
                                    enc_Wih, dec_Wih, Wref);

    k_decoder<<<NB_DEC, 256>>>(dec_Whh, dec_bih, dec_bhh, v);

    k_final<<<(Bq * (Sq - 1) + Bq * Sq + 255) / 256, 256>>>((float*)d_out);
}